// round 1
// baseline (speedup 1.0000x reference)
#include <cuda_runtime.h>
#include <math.h>

#define BB 4
#define SQ 2048
#define SK 2048
#define DD 1024
#define HH 16
#define HDIM 64

// Scratch: Q/K/V in [B,H,S,HD] layout (fp32). Static device arrays — no allocs.
__device__ float g_q[(size_t)BB * HH * SQ * HDIM];
__device__ float g_k[(size_t)BB * HH * SK * HDIM];
__device__ float g_v[(size_t)BB * HH * SK * HDIM];

// ---------------------------------------------------------------------------
// QKV projection GEMM:  Y = X[M=B*S, K=D] @ W[N=D, K=D]^T, scattered into
// [B,H,S,HD] head layout.  128x128 tile, BK=8, 256 threads, 8x8 per thread.
// which: 0 -> g_q, 1 -> g_k, 2 -> g_v
// ---------------------------------------------------------------------------
__global__ __launch_bounds__(256) void qkv_gemm(const float* __restrict__ X,
                                                const float* __restrict__ W,
                                                int which) {
    __shared__ float As[8][128];
    __shared__ float Bs[8][128];

    float* dst = (which == 0) ? g_q : (which == 1) ? g_k : g_v;

    const int tid = threadIdx.x;
    const int tx  = tid & 15;
    const int ty  = tid >> 4;
    const int row0 = blockIdx.y * 128;
    const int col0 = blockIdx.x * 128;

    float acc[8][8];
#pragma unroll
    for (int i = 0; i < 8; i++)
#pragma unroll
        for (int j = 0; j < 8; j++) acc[i][j] = 0.0f;

    const int lm = tid >> 1;          // 0..127
    const int lk = (tid & 1) * 4;     // 0 or 4
    const float* Xp = X + (size_t)(row0 + lm) * DD + lk;
    const float* Wp = W + (size_t)(col0 + lm) * DD + lk;

    for (int k0 = 0; k0 < DD; k0 += 8) {
        float4 av = *(const float4*)(Xp + k0);
        float4 bv = *(const float4*)(Wp + k0);
        As[lk + 0][lm] = av.x; As[lk + 1][lm] = av.y;
        As[lk + 2][lm] = av.z; As[lk + 3][lm] = av.w;
        Bs[lk + 0][lm] = bv.x; Bs[lk + 1][lm] = bv.y;
        Bs[lk + 2][lm] = bv.z; Bs[lk + 3][lm] = bv.w;
        __syncthreads();

#pragma unroll
        for (int k = 0; k < 8; k++) {
            float a[8], b[8];
            *(float4*)&a[0] = *(const float4*)&As[k][ty * 8];
            *(float4*)&a[4] = *(const float4*)&As[k][ty * 8 + 4];
            *(float4*)&b[0] = *(const float4*)&Bs[k][tx * 8];
            *(float4*)&b[4] = *(const float4*)&Bs[k][tx * 8 + 4];
#pragma unroll
            for (int i = 0; i < 8; i++)
#pragma unroll
                for (int j = 0; j < 8; j++)
                    acc[i][j] = fmaf(a[i], b[j], acc[i][j]);
        }
        __syncthreads();
    }

    // scatter into [B,H,S,HD]
#pragma unroll
    for (int i = 0; i < 8; i++) {
        int m = row0 + ty * 8 + i;
        int bidx = m / SQ;
        int s    = m - bidx * SQ;
#pragma unroll
        for (int j = 0; j < 8; j++) {
            int n  = col0 + tx * 8 + j;
            int h  = n >> 6;         // / HDIM
            int hd = n & 63;         // % HDIM
            dst[(((size_t)bidx * HH + h) * SQ + s) * HDIM + hd] = acc[i][j];
        }
    }
}

// ---------------------------------------------------------------------------
// Fused flash attention (fp32, no mask): per (b,h), 64-query x 64-key tiles.
// 256 threads as 16x16; each thread owns a 4x4 micro-tile of S and of ctx.
// Q,K stored d-major (transposed) in smem; V natural; P staged in smem.
// Softmax scale 1/sqrt(HD)=0.125 folded into Q at load.
// ---------------------------------------------------------------------------
#define SMW 68   // padded row width (floats)

__global__ __launch_bounds__(256) void attn_kernel(float* __restrict__ out) {
    extern __shared__ float sm[];
    float* Qs = sm;                 // [64][SMW]  Qs[d][q]
    float* Ks = Qs + 64 * SMW;      // [64][SMW]  Ks[d][kq]
    float* Vs = Ks + 64 * SMW;      // [64][SMW]  Vs[kq][hd]
    float* Ps = Vs + 64 * SMW;      // [64][SMW]  Ps[q][kq]

    const int tid = threadIdx.x;
    const int tx  = tid & 15;
    const int ty  = tid >> 4;
    const int q0  = blockIdx.x * 64;
    const int h   = blockIdx.y;
    const int b   = blockIdx.z;

    const float* Qg  = g_q + (((size_t)b * HH + h) * SQ + q0) * HDIM;
    const float* Kg0 = g_k + ((size_t)b * HH + h) * SK * HDIM;
    const float* Vg0 = g_v + ((size_t)b * HH + h) * SK * HDIM;

    // Load Q tile transposed, with softmax scale folded in.
    const float scale = 0.125f;
    for (int t = tid; t < 64 * 16; t += 256) {
        int r = t >> 4;
        int c = (t & 15) << 2;
        float4 v = *(const float4*)(Qg + r * HDIM + c);
        Qs[(c + 0) * SMW + r] = v.x * scale;
        Qs[(c + 1) * SMW + r] = v.y * scale;
        Qs[(c + 2) * SMW + r] = v.z * scale;
        Qs[(c + 3) * SMW + r] = v.w * scale;
    }

    float m_i[4], l_i[4], ctx[4][4];
#pragma unroll
    for (int i = 0; i < 4; i++) {
        m_i[i] = -1e30f;
        l_i[i] = 0.0f;
#pragma unroll
        for (int j = 0; j < 4; j++) ctx[i][j] = 0.0f;
    }

    for (int kt = 0; kt < SK; kt += 64) {
        // Load K tile (transposed) and V tile (natural).
        for (int t = tid; t < 64 * 16; t += 256) {
            int r = t >> 4;
            int c = (t & 15) << 2;
            float4 kv = *(const float4*)(Kg0 + (size_t)(kt + r) * HDIM + c);
            Ks[(c + 0) * SMW + r] = kv.x;
            Ks[(c + 1) * SMW + r] = kv.y;
            Ks[(c + 2) * SMW + r] = kv.z;
            Ks[(c + 3) * SMW + r] = kv.w;
            float4 vv = *(const float4*)(Vg0 + (size_t)(kt + r) * HDIM + c);
            *(float4*)(Vs + r * SMW + c) = vv;
        }
        __syncthreads();

        // S = (Q*scale) @ K^T   -> 4x4 per thread
        float s[4][4];
#pragma unroll
        for (int i = 0; i < 4; i++)
#pragma unroll
            for (int j = 0; j < 4; j++) s[i][j] = 0.0f;

#pragma unroll 16
        for (int d = 0; d < 64; d++) {
            float a[4], bb[4];
            *(float4*)a  = *(const float4*)(Qs + d * SMW + ty * 4);
            *(float4*)bb = *(const float4*)(Ks + d * SMW + tx * 4);
#pragma unroll
            for (int i = 0; i < 4; i++)
#pragma unroll
                for (int j = 0; j < 4; j++)
                    s[i][j] = fmaf(a[i], bb[j], s[i][j]);
        }

        // Online softmax update (row stats reduced across the 16 tx lanes;
        // lanes of one row group sit inside one half-warp, so xor-shuffles
        // with offsets <16 stay in-group).
#pragma unroll
        for (int i = 0; i < 4; i++) {
            float mx = fmaxf(fmaxf(s[i][0], s[i][1]), fmaxf(s[i][2], s[i][3]));
#pragma unroll
            for (int o = 8; o > 0; o >>= 1)
                mx = fmaxf(mx, __shfl_xor_sync(0xffffffffu, mx, o));
            float newm = fmaxf(m_i[i], mx);
            float corr = __expf(m_i[i] - newm);
            float ps = 0.0f;
#pragma unroll
            for (int j = 0; j < 4; j++) {
                s[i][j] = __expf(s[i][j] - newm);
                ps += s[i][j];
            }
#pragma unroll
            for (int o = 8; o > 0; o >>= 1)
                ps += __shfl_xor_sync(0xffffffffu, ps, o);
            l_i[i] = l_i[i] * corr + ps;
            m_i[i] = newm;
#pragma unroll
            for (int j = 0; j < 4; j++) ctx[i][j] *= corr;
        }

        // Stage P to smem for the PV GEMM.
#pragma unroll
        for (int i = 0; i < 4; i++)
            *(float4*)(Ps + (ty * 4 + i) * SMW + tx * 4) = *(float4*)s[i];
        __syncthreads();

        // ctx += P @ V
#pragma unroll 16
        for (int kk = 0; kk < 64; kk++) {
            float bb[4];
            *(float4*)bb = *(const float4*)(Vs + kk * SMW + tx * 4);
#pragma unroll
            for (int i = 0; i < 4; i++) {
                float a = Ps[(ty * 4 + i) * SMW + kk];
#pragma unroll
                for (int j = 0; j < 4; j++)
                    ctx[i][j] = fmaf(a, bb[j], ctx[i][j]);
            }
        }
        __syncthreads();   // protects Ks/Vs/Ps overwrite next tile
    }

    // Normalize and write out[b, q, h*64 + hd]
#pragma unroll
    for (int i = 0; i < 4; i++) {
        float inv = 1.0f / l_i[i];
        int q = q0 + ty * 4 + i;
        float* op = out + ((size_t)b * SQ + q) * DD + h * HDIM + tx * 4;
        float4 o;
        o.x = ctx[i][0] * inv;
        o.y = ctx[i][1] * inv;
        o.z = ctx[i][2] * inv;
        o.w = ctx[i][3] * inv;
        *(float4*)op = o;
    }
}

// ---------------------------------------------------------------------------
extern "C" void kernel_launch(void* const* d_in, const int* in_sizes, int n_in,
                              void* d_out, int out_size) {
    const float* hs  = (const float*)d_in[0];   // hidden_states   [B,SQ,D]
    const float* ehs = (const float*)d_in[1];   // encoder_hidden  [B,SK,D]
    const float* Wq  = (const float*)d_in[2];   // [D,D]
    const float* Wk  = (const float*)d_in[3];
    const float* Wv  = (const float*)d_in[4];
    float* out = (float*)d_out;

    dim3 gblk(256);
    dim3 ggrid(DD / 128, (BB * SQ) / 128);
    qkv_gemm<<<ggrid, gblk>>>(hs,  Wq, 0);
    qkv_gemm<<<ggrid, gblk>>>(ehs, Wk, 1);
    qkv_gemm<<<ggrid, gblk>>>(ehs, Wv, 2);

    size_t smem = (size_t)4 * 64 * SMW * sizeof(float);   // 69632 B
    cudaFuncSetAttribute(attn_kernel,
                         cudaFuncAttributeMaxDynamicSharedMemorySize,
                         (int)smem);
    attn_kernel<<<dim3(SQ / 64, HH, BB), 256, smem>>>(out);
}

// round 4
// speedup vs baseline: 3.1975x; 3.1975x over previous
#include <cuda_runtime.h>
#include <cuda_bf16.h>
#include <cstdint>
#include <math.h>

#define BB 4
#define SQ 2048
#define SK 2048
#define DD 1024
#define HH 16
#define HDIM 64

typedef __nv_bfloat16 bf16;

// ---------------------------------------------------------------------------
// Static device scratch (no allocations anywhere)
// ---------------------------------------------------------------------------
__device__ bf16 g_xhi[(size_t)BB * SQ * DD];
__device__ bf16 g_xlo[(size_t)BB * SQ * DD];
__device__ bf16 g_ehi[(size_t)BB * SK * DD];
__device__ bf16 g_elo[(size_t)BB * SK * DD];
__device__ bf16 g_wqhi[(size_t)DD * DD];
__device__ bf16 g_wqlo[(size_t)DD * DD];
__device__ bf16 g_wkhi[(size_t)DD * DD];
__device__ bf16 g_wklo[(size_t)DD * DD];
__device__ bf16 g_wvhi[(size_t)DD * DD];
__device__ bf16 g_wvlo[(size_t)DD * DD];

// projected Q/K/V in [B,H,S,HD] layout, bf16 hi/lo (Q pre-scaled by 0.125*log2e)
__device__ bf16 g_qhi[(size_t)BB * HH * SQ * HDIM];
__device__ bf16 g_qlo[(size_t)BB * HH * SQ * HDIM];
__device__ bf16 g_khi[(size_t)BB * HH * SK * HDIM];
__device__ bf16 g_klo[(size_t)BB * HH * SK * HDIM];
__device__ bf16 g_vhi[(size_t)BB * HH * SK * HDIM];
__device__ bf16 g_vlo[(size_t)BB * HH * SK * HDIM];

// ---------------------------------------------------------------------------
// PTX helpers (baseline sm_80+ features only — harness targets plain sm_103)
// ---------------------------------------------------------------------------
__device__ __forceinline__ uint32_t smem_u32(const void* p) {
    uint32_t a;
    asm("{ .reg .u64 t; cvta.to.shared.u64 t, %1; cvt.u32.u64 %0, t; }"
        : "=r"(a) : "l"(p));
    return a;
}

__device__ __forceinline__ void cpa16(uint32_t s, const void* g) {
    asm volatile("cp.async.ca.shared.global [%0], [%1], 16;" :: "r"(s), "l"(g));
}
#define CP_COMMIT() asm volatile("cp.async.commit_group;" ::: "memory")
#define CP_WAIT(n)  asm volatile("cp.async.wait_group %0;" :: "n"(n) : "memory")

__device__ __forceinline__ void ldsm_x4(uint32_t* r, uint32_t addr) {
    asm volatile("ldmatrix.sync.aligned.m8n8.x4.shared.b16 {%0,%1,%2,%3}, [%4];"
                 : "=r"(r[0]), "=r"(r[1]), "=r"(r[2]), "=r"(r[3]) : "r"(addr));
}
__device__ __forceinline__ void ldsm_x4_t(uint32_t* r, uint32_t addr) {
    asm volatile("ldmatrix.sync.aligned.m8n8.x4.trans.shared.b16 {%0,%1,%2,%3}, [%4];"
                 : "=r"(r[0]), "=r"(r[1]), "=r"(r[2]), "=r"(r[3]) : "r"(addr));
}

__device__ __forceinline__ void mma16816(float* c, const uint32_t* a,
                                         const uint32_t* b) {
    asm volatile(
        "mma.sync.aligned.m16n8k16.row.col.f32.bf16.bf16.f32 "
        "{%0,%1,%2,%3}, {%4,%5,%6,%7}, {%8,%9}, {%0,%1,%2,%3};"
        : "+f"(c[0]), "+f"(c[1]), "+f"(c[2]), "+f"(c[3])
        : "r"(a[0]), "r"(a[1]), "r"(a[2]), "r"(a[3]), "r"(b[0]), "r"(b[1]));
}

__device__ __forceinline__ float ex2f(float x) {
    float y;
    asm("ex2.approx.ftz.f32 %0, %1;" : "=f"(y) : "f"(x));
    return y;
}

// pack two fp32 into bf16x2 (lo = a, hi = b), round-to-nearest
__device__ __forceinline__ uint32_t pack_bf2(float a, float b) {
    uint32_t r;
    asm("cvt.rn.bf16x2.f32 %0, %1, %2;" : "=r"(r) : "f"(b), "f"(a));
    return r;
}

// split pair (s0, s1) into hi (truncated) and lo bf16x2 packs
__device__ __forceinline__ void psplit(float s0, float s1, uint32_t& h,
                                       uint32_t& l) {
    h = __byte_perm(__float_as_uint(s0), __float_as_uint(s1), 0x7632);
    float f0 = __uint_as_float(__float_as_uint(s0) & 0xffff0000u);
    float f1 = __uint_as_float(__float_as_uint(s1) & 0xffff0000u);
    l = pack_bf2(s0 - f0, s1 - f1);
}

// ---------------------------------------------------------------------------
// fp32 -> (hi, lo) bf16 split of inputs
// ---------------------------------------------------------------------------
__global__ void split_kernel(const float* __restrict__ x, bf16* __restrict__ hi,
                             bf16* __restrict__ lo, int n4) {
    int i = blockIdx.x * blockDim.x + threadIdx.x;
    if (i >= n4) return;
    float4 v = ((const float4*)x)[i];
    uint32_t h0, l0, h1, l1;
    {
        uint32_t hp = pack_bf2(v.x, v.y);
        float f0 = __uint_as_float(hp << 16);
        float f1 = __uint_as_float(hp & 0xffff0000u);
        h0 = hp;
        l0 = pack_bf2(v.x - f0, v.y - f1);
    }
    {
        uint32_t hp = pack_bf2(v.z, v.w);
        float f0 = __uint_as_float(hp << 16);
        float f1 = __uint_as_float(hp & 0xffff0000u);
        h1 = hp;
        l1 = pack_bf2(v.z - f0, v.w - f1);
    }
    ((uint2*)hi)[i] = make_uint2(h0, h1);
    ((uint2*)lo)[i] = make_uint2(l0, l1);
}

// ---------------------------------------------------------------------------
// Projection GEMM (HMMA, bf16 3-term split): C[M,1024] = X @ W^T
// Block 128x128, BK=32, 256 thr (8 warps: 2m x 4n, warp tile 64x32).
// ---------------------------------------------------------------------------
#define PARR 10240u     // bytes per smem array (128 rows * 80B stride)
#define PBUF 40960u     // bytes per buffer (4 arrays)

__global__ __launch_bounds__(256) void proj_tc(
    const bf16* __restrict__ xh, const bf16* __restrict__ xl,
    const bf16* __restrict__ wh, const bf16* __restrict__ wl, int which) {
    extern __shared__ char smc[];
    const uint32_t smb = smem_u32(smc);
    const int tid = threadIdx.x;
    const int wid = tid >> 5, lane = tid & 31;
    const int gid = lane >> 2, tig = lane & 3;
    const int wm = wid & 1, wn = wid >> 1;
    const int n0 = blockIdx.x * 128;
    const int m0 = blockIdx.y * 128;

    float acc[4][4][4];
#pragma unroll
    for (int a = 0; a < 4; a++)
#pragma unroll
        for (int bq = 0; bq < 4; bq++)
#pragma unroll
            for (int c = 0; c < 4; c++) acc[a][bq][c] = 0.0f;

    // tile loader: 4 arrays * 128 rows * 4 segs(16B) = 2048 chunks / 256 thr
    auto load_tile = [&](int kc, int p) {
        const int k0 = kc * 32;
        const uint32_t base = smb + p * PBUF;
#pragma unroll
        for (int i = 0; i < 8; i++) {
            int c = tid + i * 256;
            int arr = c >> 9;
            int row = (c >> 2) & 127;
            int seg = c & 3;
            const bf16* g;
            if (arr == 0)      g = xh + (size_t)(m0 + row) * DD + k0 + seg * 8;
            else if (arr == 1) g = xl + (size_t)(m0 + row) * DD + k0 + seg * 8;
            else if (arr == 2) g = wh + (size_t)(n0 + row) * DD + k0 + seg * 8;
            else               g = wl + (size_t)(n0 + row) * DD + k0 + seg * 8;
            cpa16(base + arr * PARR + row * 80 + seg * 16, g);
        }
        CP_COMMIT();
    };

    const int rowA = lane & 15, colA = (lane >> 4) * 8;
    const int rowB = (lane & 7) + ((lane >> 4) << 3);
    const int colB = ((lane >> 3) & 1) * 8;

    load_tile(0, 0);
    for (int t = 0; t < 32; t++) {
        if (t + 1 < 32) {
            load_tile(t + 1, (t + 1) & 1);
            CP_WAIT(1);
        } else {
            CP_WAIT(0);
        }
        __syncthreads();

        const uint32_t bbase = smb + (t & 1) * PBUF;
        const uint32_t Xh_s = bbase, Xl_s = bbase + PARR;
        const uint32_t Wh_s = bbase + 2 * PARR, Wl_s = bbase + 3 * PARR;

#pragma unroll
        for (int ks = 0; ks < 2; ks++) {
            const int k0s = ks * 16;
            uint32_t bh[2][4], bl[2][4];
#pragma unroll
            for (int np = 0; np < 2; np++) {
                uint32_t ad = (wn * 32 + np * 16 + rowB) * 80 + (k0s + colB) * 2;
                ldsm_x4(bh[np], Wh_s + ad);
                ldsm_x4(bl[np], Wl_s + ad);
            }
#pragma unroll
            for (int mt = 0; mt < 4; mt++) {
                uint32_t ah[4], al[4];
                uint32_t ad = (wm * 64 + mt * 16 + rowA) * 80 + (k0s + colA) * 2;
                ldsm_x4(ah, Xh_s + ad);
                ldsm_x4(al, Xl_s + ad);
#pragma unroll
                for (int nt = 0; nt < 4; nt++) {
                    const uint32_t* bhp = &bh[nt >> 1][(nt & 1) * 2];
                    const uint32_t* blp = &bl[nt >> 1][(nt & 1) * 2];
                    mma16816(acc[mt][nt], ah, bhp);
                    mma16816(acc[mt][nt], ah, blp);
                    mma16816(acc[mt][nt], al, bhp);
                }
            }
        }
        __syncthreads();
    }

    // epilogue: split-write into head layout
    bf16* dh = (which == 0) ? g_qhi : (which == 1) ? g_khi : g_vhi;
    bf16* dl = (which == 0) ? g_qlo : (which == 1) ? g_klo : g_vlo;
    const float qs = (which == 0) ? (0.125f * 1.4426950408889634f) : 1.0f;

#pragma unroll
    for (int mt = 0; mt < 4; mt++) {
        int m = m0 + wm * 64 + mt * 16 + gid;
        int bb = m >> 11;
        int s = m & (SQ - 1);
#pragma unroll
        for (int nt = 0; nt < 4; nt++) {
            int n = n0 + wn * 32 + nt * 8 + 2 * tig;
            int head = n >> 6;
            int hd = n & 63;
            size_t idx = (((size_t)bb * HH + head) * SQ + s) * HDIM + hd;
            {
                float c0 = acc[mt][nt][0] * qs, c1 = acc[mt][nt][1] * qs;
                uint32_t hp = pack_bf2(c0, c1);
                float f0 = __uint_as_float(hp << 16);
                float f1 = __uint_as_float(hp & 0xffff0000u);
                *(uint32_t*)(dh + idx) = hp;
                *(uint32_t*)(dl + idx) = pack_bf2(c0 - f0, c1 - f1);
            }
            {
                float c0 = acc[mt][nt][2] * qs, c1 = acc[mt][nt][3] * qs;
                uint32_t hp = pack_bf2(c0, c1);
                float f0 = __uint_as_float(hp << 16);
                float f1 = __uint_as_float(hp & 0xffff0000u);
                *(uint32_t*)(dh + idx + 8 * HDIM) = hp;
                *(uint32_t*)(dl + idx + 8 * HDIM) = pack_bf2(c0 - f0, c1 - f1);
            }
        }
    }
}

// ---------------------------------------------------------------------------
// Flash attention (HMMA, split precision). Block = 64 queries, 4 warps.
// Warp: 16 q rows x 64 keys per tile; P kept in registers (acc->A remap).
// Each smem row = 64 bf16 = 128 bytes = 8 x 16B chunks (stride 144B).
// ---------------------------------------------------------------------------
#define AST 144u      // smem row stride bytes (72 bf16)
#define AARR 9216u    // 64 * 144
#define AKVBUF 36864u // 4 arrays per buffer

__global__ __launch_bounds__(128) void attn_tc(float* __restrict__ out) {
    extern __shared__ char smc[];
    const uint32_t smb = smem_u32(smc);
    const int tid = threadIdx.x;
    const int wid = tid >> 5, lane = tid & 31;
    const int gid = lane >> 2, tig = lane & 3;
    const int q0 = blockIdx.x * 64;
    const int h = blockIdx.y, b = blockIdx.z;

    const size_t bh = (size_t)b * HH + h;
    const bf16* Qh_g = g_qhi + (bh * SQ + q0) * HDIM;
    const bf16* Ql_g = g_qlo + (bh * SQ + q0) * HDIM;
    const bf16* Kh_g = g_khi + bh * SK * HDIM;
    const bf16* Kl_g = g_klo + bh * SK * HDIM;
    const bf16* Vh_g = g_vhi + bh * SK * HDIM;
    const bf16* Vl_g = g_vlo + bh * SK * HDIM;

    const uint32_t Qh_s = smb, Ql_s = smb + AARR;
    const uint32_t KV_s = smb + 2 * AARR;

    // Q load: 2 arrays * 64 rows * 8 segs = 1024 chunks / 128 thr = 8 each
#pragma unroll
    for (int i = 0; i < 8; i++) {
        int c = tid + i * 128;
        int arr = c >> 9;
        int row = (c >> 3) & 63;
        int seg = c & 7;
        const bf16* g = (arr ? Ql_g : Qh_g) + row * HDIM + seg * 8;
        cpa16((arr ? Ql_s : Qh_s) + row * AST + seg * 16, g);
    }
    CP_COMMIT();

    // KV load: 4 arrays * 64 rows * 8 segs = 2048 chunks / 128 thr = 16 each
    auto load_kv = [&](int kt, int p) {
        const uint32_t base = KV_s + p * AKVBUF;
        const int key0 = kt * 64;
#pragma unroll
        for (int i = 0; i < 16; i++) {
            int c = tid + i * 128;
            int arr = c >> 9;
            int row = (c >> 3) & 63;
            int seg = c & 7;
            const bf16* g;
            if (arr == 0)      g = Kh_g + (size_t)(key0 + row) * HDIM + seg * 8;
            else if (arr == 1) g = Kl_g + (size_t)(key0 + row) * HDIM + seg * 8;
            else if (arr == 2) g = Vh_g + (size_t)(key0 + row) * HDIM + seg * 8;
            else               g = Vl_g + (size_t)(key0 + row) * HDIM + seg * 8;
            cpa16(base + arr * AARR + row * AST + seg * 16, g);
        }
        CP_COMMIT();
    };

    load_kv(0, 0);
    CP_WAIT(1);   // Q group done; tile 0 may still be in flight
    __syncthreads();

    // preload Q fragments
    uint32_t qh[4][4], ql[4][4];
    const int rowA = lane & 15, colA = (lane >> 4) * 8;
#pragma unroll
    for (int kk = 0; kk < 4; kk++) {
        uint32_t ad = (wid * 16 + rowA) * AST + (kk * 16 + colA) * 2;
        ldsm_x4(qh[kk], Qh_s + ad);
        ldsm_x4(ql[kk], Ql_s + ad);
    }

    float ctx[8][4];
#pragma unroll
    for (int t = 0; t < 8; t++)
#pragma unroll
        for (int c = 0; c < 4; c++) ctx[t][c] = 0.0f;
    float m_a = -1e30f, m_b = -1e30f, l_a = 0.0f, l_b = 0.0f;

    const int rowB = (lane & 7) + ((lane >> 4) << 3);
    const int colB = ((lane >> 3) & 1) * 8;
    const int rowV = (lane & 7) + (((lane >> 3) & 1) << 3);
    const int colV = (lane >> 4) << 3;

    const int NT = SK / 64;
    for (int t = 0; t < NT; t++) {
        if (t + 1 < NT) {
            load_kv(t + 1, (t + 1) & 1);
            CP_WAIT(1);
        } else {
            CP_WAIT(0);
        }
        __syncthreads();

        const uint32_t kb = KV_s + (t & 1) * AKVBUF;
        const uint32_t Kh_sm = kb, Kl_sm = kb + AARR;
        const uint32_t Vh_sm = kb + 2 * AARR, Vl_sm = kb + 3 * AARR;

        // S = Q K^T (3-term split)
        float s[8][4];
#pragma unroll
        for (int tt = 0; tt < 8; tt++)
#pragma unroll
            for (int c = 0; c < 4; c++) s[tt][c] = 0.0f;

#pragma unroll
        for (int kk = 0; kk < 4; kk++) {
#pragma unroll
            for (int nn = 0; nn < 4; nn++) {
                uint32_t kh[4], kl[4];
                uint32_t ad = (nn * 16 + rowB) * AST + (kk * 16 + colB) * 2;
                ldsm_x4(kh, Kh_sm + ad);
                ldsm_x4(kl, Kl_sm + ad);
                mma16816(s[2 * nn], qh[kk], kh);
                mma16816(s[2 * nn], qh[kk], kl);
                mma16816(s[2 * nn], ql[kk], kh);
                mma16816(s[2 * nn + 1], qh[kk], kh + 2);
                mma16816(s[2 * nn + 1], qh[kk], kl + 2);
                mma16816(s[2 * nn + 1], ql[kk], kh + 2);
            }
        }

        // online softmax (S already in log2 domain via pre-scaled Q)
        float mA = s[0][0], mB = s[0][2];
#pragma unroll
        for (int tt = 0; tt < 8; tt++) {
            mA = fmaxf(mA, fmaxf(s[tt][0], s[tt][1]));
            mB = fmaxf(mB, fmaxf(s[tt][2], s[tt][3]));
        }
        mA = fmaxf(mA, __shfl_xor_sync(0xffffffffu, mA, 1));
        mA = fmaxf(mA, __shfl_xor_sync(0xffffffffu, mA, 2));
        mB = fmaxf(mB, __shfl_xor_sync(0xffffffffu, mB, 1));
        mB = fmaxf(mB, __shfl_xor_sync(0xffffffffu, mB, 2));
        float nmA = fmaxf(m_a, mA), nmB = fmaxf(m_b, mB);
        float corrA = ex2f(m_a - nmA), corrB = ex2f(m_b - nmB);

        float rA = 0.0f, rB = 0.0f;
#pragma unroll
        for (int tt = 0; tt < 8; tt++) {
            s[tt][0] = ex2f(s[tt][0] - nmA);
            s[tt][1] = ex2f(s[tt][1] - nmA);
            s[tt][2] = ex2f(s[tt][2] - nmB);
            s[tt][3] = ex2f(s[tt][3] - nmB);
            rA += s[tt][0] + s[tt][1];
            rB += s[tt][2] + s[tt][3];
        }
        rA += __shfl_xor_sync(0xffffffffu, rA, 1);
        rA += __shfl_xor_sync(0xffffffffu, rA, 2);
        rB += __shfl_xor_sync(0xffffffffu, rB, 1);
        rB += __shfl_xor_sync(0xffffffffu, rB, 2);
        l_a = l_a * corrA + rA;
        l_b = l_b * corrB + rB;
        m_a = nmA;
        m_b = nmB;
#pragma unroll
        for (int tt = 0; tt < 8; tt++) {
            ctx[tt][0] *= corrA;
            ctx[tt][1] *= corrA;
            ctx[tt][2] *= corrB;
            ctx[tt][3] *= corrB;
        }

        // ctx += P V  (P split in registers)
#pragma unroll
        for (int j = 0; j < 4; j++) {
            uint32_t ah[4], al[4];
            psplit(s[2 * j][0], s[2 * j][1], ah[0], al[0]);
            psplit(s[2 * j][2], s[2 * j][3], ah[1], al[1]);
            psplit(s[2 * j + 1][0], s[2 * j + 1][1], ah[2], al[2]);
            psplit(s[2 * j + 1][2], s[2 * j + 1][3], ah[3], al[3]);
#pragma unroll
            for (int hp = 0; hp < 4; hp++) {
                uint32_t vh[4], vl[4];
                uint32_t ad = (j * 16 + rowV) * AST + (hp * 16 + colV) * 2;
                ldsm_x4_t(vh, Vh_sm + ad);
                ldsm_x4_t(vl, Vl_sm + ad);
                mma16816(ctx[2 * hp], ah, vh);
                mma16816(ctx[2 * hp], ah, vl);
                mma16816(ctx[2 * hp], al, vh);
                mma16816(ctx[2 * hp + 1], ah, vh + 2);
                mma16816(ctx[2 * hp + 1], ah, vl + 2);
                mma16816(ctx[2 * hp + 1], al, vh + 2);
            }
        }
        __syncthreads();
    }

    // epilogue
    float invA = 1.0f / l_a, invB = 1.0f / l_b;
    int qA = q0 + wid * 16 + gid;
    float* oA = out + ((size_t)b * SQ + qA) * DD + h * HDIM;
    float* oB = oA + (size_t)8 * DD;
#pragma unroll
    for (int tt = 0; tt < 8; tt++) {
        int hd = 8 * tt + 2 * tig;
        float2 a2 = make_float2(ctx[tt][0] * invA, ctx[tt][1] * invA);
        float2 b2 = make_float2(ctx[tt][2] * invB, ctx[tt][3] * invB);
        *(float2*)(oA + hd) = a2;
        *(float2*)(oB + hd) = b2;
    }
}

// ---------------------------------------------------------------------------
extern "C" void kernel_launch(void* const* d_in, const int* in_sizes, int n_in,
                              void* d_out, int out_size) {
    const float* hs = (const float*)d_in[0];
    const float* ehs = (const float*)d_in[1];
    const float* Wq = (const float*)d_in[2];
    const float* Wk = (const float*)d_in[3];
    const float* Wv = (const float*)d_in[4];
    float* out = (float*)d_out;

    bf16 *xhi, *xlo, *ehi, *elo, *wqh, *wql, *wkh, *wkl, *wvh, *wvl;
    cudaGetSymbolAddress((void**)&xhi, g_xhi);
    cudaGetSymbolAddress((void**)&xlo, g_xlo);
    cudaGetSymbolAddress((void**)&ehi, g_ehi);
    cudaGetSymbolAddress((void**)&elo, g_elo);
    cudaGetSymbolAddress((void**)&wqh, g_wqhi);
    cudaGetSymbolAddress((void**)&wql, g_wqlo);
    cudaGetSymbolAddress((void**)&wkh, g_wkhi);
    cudaGetSymbolAddress((void**)&wkl, g_wklo);
    cudaGetSymbolAddress((void**)&wvh, g_wvhi);
    cudaGetSymbolAddress((void**)&wvl, g_wvlo);

    {
        int n4 = (BB * SQ * DD) / 4;
        split_kernel<<<(n4 + 255) / 256, 256>>>(hs, xhi, xlo, n4);
        split_kernel<<<(n4 + 255) / 256, 256>>>(ehs, ehi, elo, n4);
        int w4 = (DD * DD) / 4;
        split_kernel<<<(w4 + 255) / 256, 256>>>(Wq, wqh, wql, w4);
        split_kernel<<<(w4 + 255) / 256, 256>>>(Wk, wkh, wkl, w4);
        split_kernel<<<(w4 + 255) / 256, 256>>>(Wv, wvh, wvl, w4);
    }

    {
        size_t smem = 2 * PBUF;  // 81920
        cudaFuncSetAttribute(proj_tc, cudaFuncAttributeMaxDynamicSharedMemorySize,
                             (int)smem);
        dim3 grid(DD / 128, (BB * SQ) / 128);
        proj_tc<<<grid, 256, smem>>>(xhi, xlo, wqh, wql, 0);
        proj_tc<<<grid, 256, smem>>>(ehi, elo, wkh, wkl, 1);
        proj_tc<<<grid, 256, smem>>>(ehi, elo, wvh, wvl, 2);
    }

    {
        size_t smem = 2 * AARR + 2 * AKVBUF;  // 92160
        cudaFuncSetAttribute(attn_tc, cudaFuncAttributeMaxDynamicSharedMemorySize,
                             (int)smem);
        attn_tc<<<dim3(SQ / 64, HH, BB), 128, smem>>>(out);
    }
}

// round 5
// speedup vs baseline: 3.3342x; 1.0428x over previous
#include <cuda_runtime.h>
#include <cuda_bf16.h>
#include <cstdint>
#include <math.h>

#define BB 4
#define SQ 2048
#define SK 2048
#define DD 1024
#define HH 16
#define HDIM 64

typedef __nv_bfloat16 bf16;

// ---------------------------------------------------------------------------
// Static device scratch (no allocations anywhere)
// ---------------------------------------------------------------------------
__device__ bf16 g_xhi[(size_t)BB * SQ * DD];
__device__ bf16 g_xlo[(size_t)BB * SQ * DD];
__device__ bf16 g_ehi[(size_t)BB * SK * DD];
__device__ bf16 g_elo[(size_t)BB * SK * DD];
__device__ bf16 g_wqhi[(size_t)DD * DD];
__device__ bf16 g_wqlo[(size_t)DD * DD];
__device__ bf16 g_wkhi[(size_t)DD * DD];
__device__ bf16 g_wklo[(size_t)DD * DD];
__device__ bf16 g_wvhi[(size_t)DD * DD];
__device__ bf16 g_wvlo[(size_t)DD * DD];

// projected Q/K/V in [B,H,S,HD] layout, bf16 hi/lo (Q pre-scaled by 0.125*log2e)
__device__ bf16 g_qhi[(size_t)BB * HH * SQ * HDIM];
__device__ bf16 g_qlo[(size_t)BB * HH * SQ * HDIM];
__device__ bf16 g_khi[(size_t)BB * HH * SK * HDIM];
__device__ bf16 g_klo[(size_t)BB * HH * SK * HDIM];
__device__ bf16 g_vhi[(size_t)BB * HH * SK * HDIM];
__device__ bf16 g_vlo[(size_t)BB * HH * SK * HDIM];

// ---------------------------------------------------------------------------
// PTX helpers (baseline sm_80+ features only — harness targets plain sm_103)
// ---------------------------------------------------------------------------
__device__ __forceinline__ uint32_t smem_u32(const void* p) {
    uint32_t a;
    asm("{ .reg .u64 t; cvta.to.shared.u64 t, %1; cvt.u32.u64 %0, t; }"
        : "=r"(a) : "l"(p));
    return a;
}

__device__ __forceinline__ void cpa16(uint32_t s, const void* g) {
    asm volatile("cp.async.ca.shared.global [%0], [%1], 16;" :: "r"(s), "l"(g));
}
#define CP_COMMIT() asm volatile("cp.async.commit_group;" ::: "memory")
#define CP_WAIT(n)  asm volatile("cp.async.wait_group %0;" :: "n"(n) : "memory")

__device__ __forceinline__ void ldsm_x4(uint32_t* r, uint32_t addr) {
    asm volatile("ldmatrix.sync.aligned.m8n8.x4.shared.b16 {%0,%1,%2,%3}, [%4];"
                 : "=r"(r[0]), "=r"(r[1]), "=r"(r[2]), "=r"(r[3]) : "r"(addr));
}
__device__ __forceinline__ void ldsm_x4_t(uint32_t* r, uint32_t addr) {
    asm volatile("ldmatrix.sync.aligned.m8n8.x4.trans.shared.b16 {%0,%1,%2,%3}, [%4];"
                 : "=r"(r[0]), "=r"(r[1]), "=r"(r[2]), "=r"(r[3]) : "r"(addr));
}

__device__ __forceinline__ void mma16816(float* c, const uint32_t* a,
                                         const uint32_t* b) {
    asm volatile(
        "mma.sync.aligned.m16n8k16.row.col.f32.bf16.bf16.f32 "
        "{%0,%1,%2,%3}, {%4,%5,%6,%7}, {%8,%9}, {%0,%1,%2,%3};"
        : "+f"(c[0]), "+f"(c[1]), "+f"(c[2]), "+f"(c[3])
        : "r"(a[0]), "r"(a[1]), "r"(a[2]), "r"(a[3]), "r"(b[0]), "r"(b[1]));
}

__device__ __forceinline__ float ex2f(float x) {
    float y;
    asm("ex2.approx.ftz.f32 %0, %1;" : "=f"(y) : "f"(x));
    return y;
}

// pack two fp32 into bf16x2 (lo = a, hi = b), round-to-nearest
__device__ __forceinline__ uint32_t pack_bf2(float a, float b) {
    uint32_t r;
    asm("cvt.rn.bf16x2.f32 %0, %1, %2;" : "=r"(r) : "f"(b), "f"(a));
    return r;
}

// split pair (s0, s1) into hi (truncated) and lo bf16x2 packs
__device__ __forceinline__ void psplit(float s0, float s1, uint32_t& h,
                                       uint32_t& l) {
    h = __byte_perm(__float_as_uint(s0), __float_as_uint(s1), 0x7632);
    float f0 = __uint_as_float(__float_as_uint(s0) & 0xffff0000u);
    float f1 = __uint_as_float(__float_as_uint(s1) & 0xffff0000u);
    l = pack_bf2(s0 - f0, s1 - f1);
}

// swizzled byte offset: 128B rows, SW128 (bits[6:4] ^= row&7)
#define ASW(row, colb) \
    ((uint32_t)(((row) << 7) + ((colb) ^ ((((uint32_t)(row)) & 7u) << 4))))

// ---------------------------------------------------------------------------
// fp32 -> (hi, lo) bf16 split of inputs
// ---------------------------------------------------------------------------
__global__ void split_kernel(const float* __restrict__ x, bf16* __restrict__ hi,
                             bf16* __restrict__ lo, int n4) {
    int i = blockIdx.x * blockDim.x + threadIdx.x;
    if (i >= n4) return;
    float4 v = ((const float4*)x)[i];
    uint32_t h0, l0, h1, l1;
    {
        uint32_t hp = pack_bf2(v.x, v.y);
        float f0 = __uint_as_float(hp << 16);
        float f1 = __uint_as_float(hp & 0xffff0000u);
        h0 = hp;
        l0 = pack_bf2(v.x - f0, v.y - f1);
    }
    {
        uint32_t hp = pack_bf2(v.z, v.w);
        float f0 = __uint_as_float(hp << 16);
        float f1 = __uint_as_float(hp & 0xffff0000u);
        h1 = hp;
        l1 = pack_bf2(v.z - f0, v.w - f1);
    }
    ((uint2*)hi)[i] = make_uint2(h0, h1);
    ((uint2*)lo)[i] = make_uint2(l0, l1);
}

// ---------------------------------------------------------------------------
// Projection GEMM (HMMA, bf16 3-term split): C[M,1024] = X @ W^T
// Block 128x128, BK=32, 256 thr (8 warps: 2m x 4n, warp tile 64x32).
// ---------------------------------------------------------------------------
#define PARR 10240u     // bytes per smem array (128 rows * 80B stride)
#define PBUF 40960u     // bytes per buffer (4 arrays)

__global__ __launch_bounds__(256) void proj_tc(
    const bf16* __restrict__ xh, const bf16* __restrict__ xl,
    const bf16* __restrict__ wh, const bf16* __restrict__ wl, int which) {
    extern __shared__ char smc[];
    const uint32_t smb = smem_u32(smc);
    const int tid = threadIdx.x;
    const int wid = tid >> 5, lane = tid & 31;
    const int gid = lane >> 2, tig = lane & 3;
    const int wm = wid & 1, wn = wid >> 1;
    const int n0 = blockIdx.x * 128;
    const int m0 = blockIdx.y * 128;

    float acc[4][4][4];
#pragma unroll
    for (int a = 0; a < 4; a++)
#pragma unroll
        for (int bq = 0; bq < 4; bq++)
#pragma unroll
            for (int c = 0; c < 4; c++) acc[a][bq][c] = 0.0f;

    // tile loader: 4 arrays * 128 rows * 4 segs(16B) = 2048 chunks / 256 thr
    auto load_tile = [&](int kc, int p) {
        const int k0 = kc * 32;
        const uint32_t base = smb + p * PBUF;
#pragma unroll
        for (int i = 0; i < 8; i++) {
            int c = tid + i * 256;
            int arr = c >> 9;
            int row = (c >> 2) & 127;
            int seg = c & 3;
            const bf16* g;
            if (arr == 0)      g = xh + (size_t)(m0 + row) * DD + k0 + seg * 8;
            else if (arr == 1) g = xl + (size_t)(m0 + row) * DD + k0 + seg * 8;
            else if (arr == 2) g = wh + (size_t)(n0 + row) * DD + k0 + seg * 8;
            else               g = wl + (size_t)(n0 + row) * DD + k0 + seg * 8;
            cpa16(base + arr * PARR + row * 80 + seg * 16, g);
        }
        CP_COMMIT();
    };

    const int rowA = lane & 15, colA = (lane >> 4) * 8;
    const int rowB = (lane & 7) + ((lane >> 4) << 3);
    const int colB = ((lane >> 3) & 1) * 8;

    load_tile(0, 0);
    for (int t = 0; t < 32; t++) {
        if (t + 1 < 32) {
            load_tile(t + 1, (t + 1) & 1);
            CP_WAIT(1);
        } else {
            CP_WAIT(0);
        }
        __syncthreads();

        const uint32_t bbase = smb + (t & 1) * PBUF;
        const uint32_t Xh_s = bbase, Xl_s = bbase + PARR;
        const uint32_t Wh_s = bbase + 2 * PARR, Wl_s = bbase + 3 * PARR;

#pragma unroll
        for (int ks = 0; ks < 2; ks++) {
            const int k0s = ks * 16;
            uint32_t bh[2][4], bl[2][4];
#pragma unroll
            for (int np = 0; np < 2; np++) {
                uint32_t ad = (wn * 32 + np * 16 + rowB) * 80 + (k0s + colB) * 2;
                ldsm_x4(bh[np], Wh_s + ad);
                ldsm_x4(bl[np], Wl_s + ad);
            }
#pragma unroll
            for (int mt = 0; mt < 4; mt++) {
                uint32_t ah[4], al[4];
                uint32_t ad = (wm * 64 + mt * 16 + rowA) * 80 + (k0s + colA) * 2;
                ldsm_x4(ah, Xh_s + ad);
                ldsm_x4(al, Xl_s + ad);
#pragma unroll
                for (int nt = 0; nt < 4; nt++) {
                    const uint32_t* bhp = &bh[nt >> 1][(nt & 1) * 2];
                    const uint32_t* blp = &bl[nt >> 1][(nt & 1) * 2];
                    mma16816(acc[mt][nt], ah, bhp);
                    mma16816(acc[mt][nt], ah, blp);
                    mma16816(acc[mt][nt], al, bhp);
                }
            }
        }
        __syncthreads();
    }

    // epilogue: split-write into head layout
    bf16* dh = (which == 0) ? g_qhi : (which == 1) ? g_khi : g_vhi;
    bf16* dl = (which == 0) ? g_qlo : (which == 1) ? g_klo : g_vlo;
    const float qs = (which == 0) ? (0.125f * 1.4426950408889634f) : 1.0f;

#pragma unroll
    for (int mt = 0; mt < 4; mt++) {
        int m = m0 + wm * 64 + mt * 16 + gid;
        int bb = m >> 11;
        int s = m & (SQ - 1);
#pragma unroll
        for (int nt = 0; nt < 4; nt++) {
            int n = n0 + wn * 32 + nt * 8 + 2 * tig;
            int head = n >> 6;
            int hd = n & 63;
            size_t idx = (((size_t)bb * HH + head) * SQ + s) * HDIM + hd;
            {
                float c0 = acc[mt][nt][0] * qs, c1 = acc[mt][nt][1] * qs;
                uint32_t hp = pack_bf2(c0, c1);
                float f0 = __uint_as_float(hp << 16);
                float f1 = __uint_as_float(hp & 0xffff0000u);
                *(uint32_t*)(dh + idx) = hp;
                *(uint32_t*)(dl + idx) = pack_bf2(c0 - f0, c1 - f1);
            }
            {
                float c0 = acc[mt][nt][2] * qs, c1 = acc[mt][nt][3] * qs;
                uint32_t hp = pack_bf2(c0, c1);
                float f0 = __uint_as_float(hp << 16);
                float f1 = __uint_as_float(hp & 0xffff0000u);
                *(uint32_t*)(dh + idx + 8 * HDIM) = hp;
                *(uint32_t*)(dl + idx + 8 * HDIM) = pack_bf2(c0 - f0, c1 - f1);
            }
        }
    }
}

// ---------------------------------------------------------------------------
// Flash attention (HMMA, split precision). Block = 128 queries, 8 warps,
// warp = 16 q rows x 64 keys. Swizzled smem (SW128, 128B stride) -> 96KB/CTA
// -> 2 CTAs/SM (16 warps/SM). Q-hi fragments preloaded; Q-lo re-ldsm'd.
// ---------------------------------------------------------------------------
#define QARR 16384u    // 128 rows * 128B
#define KARR 8192u     // 64 rows * 128B
#define KVBUF 32768u   // 4 arrays

__global__ __launch_bounds__(256, 2) void attn_tc(float* __restrict__ out) {
    extern __shared__ char smc[];
    const uint32_t smb = smem_u32(smc);
    const int tid = threadIdx.x;
    const int wid = tid >> 5, lane = tid & 31;
    const int gid = lane >> 2, tig = lane & 3;
    const int q0 = blockIdx.x * 128;
    const int h = blockIdx.y, b = blockIdx.z;

    const size_t bh = (size_t)b * HH + h;
    const bf16* Qh_g = g_qhi + (bh * SQ + q0) * HDIM;
    const bf16* Ql_g = g_qlo + (bh * SQ + q0) * HDIM;
    const bf16* Kh_g = g_khi + bh * SK * HDIM;
    const bf16* Kl_g = g_klo + bh * SK * HDIM;
    const bf16* Vh_g = g_vhi + bh * SK * HDIM;
    const bf16* Vl_g = g_vlo + bh * SK * HDIM;

    const uint32_t QH = smb, QL = smb + QARR;
    const uint32_t KV = smb + 2 * QARR;

    // Q load: 2 arrays * 128 rows * 8 segs = 2048 chunks / 256 thr = 8 each
#pragma unroll
    for (int i = 0; i < 8; i++) {
        int c = tid + i * 256;
        int arr = c >> 10;
        int row = (c >> 3) & 127;
        int seg = c & 7;
        const bf16* g = (arr ? Ql_g : Qh_g) + row * HDIM + seg * 8;
        cpa16((arr ? QL : QH) + ASW(row, seg * 16), g);
    }
    CP_COMMIT();

    // KV load: 4 arrays * 64 rows * 8 segs = 2048 chunks / 256 thr = 8 each
    auto load_kv = [&](int kt, int p) {
        const uint32_t base = KV + p * KVBUF;
        const int key0 = kt * 64;
#pragma unroll
        for (int i = 0; i < 8; i++) {
            int c = tid + i * 256;
            int arr = c >> 9;
            int row = (c >> 3) & 63;
            int seg = c & 7;
            const bf16* g;
            if (arr == 0)      g = Kh_g + (size_t)(key0 + row) * HDIM + seg * 8;
            else if (arr == 1) g = Kl_g + (size_t)(key0 + row) * HDIM + seg * 8;
            else if (arr == 2) g = Vh_g + (size_t)(key0 + row) * HDIM + seg * 8;
            else               g = Vl_g + (size_t)(key0 + row) * HDIM + seg * 8;
            cpa16(base + arr * KARR + ASW(row, seg * 16), g);
        }
        CP_COMMIT();
    };

    load_kv(0, 0);
    CP_WAIT(1);   // Q group done; tile 0 may still be in flight
    __syncthreads();

    // preload Q-hi fragments (Q-lo is re-ldsm'd per use to stay <=128 regs)
    const int rowA = lane & 15;
    const int colAb = (lane >> 4) * 16;       // byte col within 32B k-step
    uint32_t qh[4][4];
#pragma unroll
    for (int kk = 0; kk < 4; kk++)
        ldsm_x4(qh[kk], QH + ASW(wid * 16 + rowA, kk * 32 + colAb));

    float ctx[8][4];
#pragma unroll
    for (int t = 0; t < 8; t++)
#pragma unroll
        for (int c = 0; c < 4; c++) ctx[t][c] = 0.0f;
    float m_a = -1e30f, m_b = -1e30f, l_a = 0.0f, l_b = 0.0f;

    const int rowB = (lane & 7) + ((lane >> 4) << 3);
    const int colBb = ((lane >> 3) & 1) * 16;
    const int rowV = (lane & 7) + (((lane >> 3) & 1) << 3);
    const int colVb = (lane >> 4) * 16;

    const int NT = SK / 64;
    for (int t = 0; t < NT; t++) {
        if (t + 1 < NT) {
            load_kv(t + 1, (t + 1) & 1);
            CP_WAIT(1);
        } else {
            CP_WAIT(0);
        }
        __syncthreads();

        const uint32_t kb = KV + (t & 1) * KVBUF;
        const uint32_t KHs = kb, KLs = kb + KARR;
        const uint32_t VHs = kb + 2 * KARR, VLs = kb + 3 * KARR;

        // S = Q K^T (3-term split)
        float s[8][4];
#pragma unroll
        for (int tt = 0; tt < 8; tt++)
#pragma unroll
            for (int c = 0; c < 4; c++) s[tt][c] = 0.0f;

#pragma unroll
        for (int kk = 0; kk < 4; kk++) {
            uint32_t ql4[4];
            ldsm_x4(ql4, QL + ASW(wid * 16 + rowA, kk * 32 + colAb));
#pragma unroll
            for (int nn = 0; nn < 4; nn++) {
                uint32_t kh[4], kl[4];
                uint32_t ad = ASW(nn * 16 + rowB, kk * 32 + colBb);
                ldsm_x4(kh, KHs + ad);
                ldsm_x4(kl, KLs + ad);
                mma16816(s[2 * nn], qh[kk], kh);
                mma16816(s[2 * nn], qh[kk], kl);
                mma16816(s[2 * nn], ql4, kh);
                mma16816(s[2 * nn + 1], qh[kk], kh + 2);
                mma16816(s[2 * nn + 1], qh[kk], kl + 2);
                mma16816(s[2 * nn + 1], ql4, kh + 2);
            }
        }

        // online softmax (S already in log2 domain via pre-scaled Q)
        float mA = s[0][0], mB = s[0][2];
#pragma unroll
        for (int tt = 0; tt < 8; tt++) {
            mA = fmaxf(mA, fmaxf(s[tt][0], s[tt][1]));
            mB = fmaxf(mB, fmaxf(s[tt][2], s[tt][3]));
        }
        mA = fmaxf(mA, __shfl_xor_sync(0xffffffffu, mA, 1));
        mA = fmaxf(mA, __shfl_xor_sync(0xffffffffu, mA, 2));
        mB = fmaxf(mB, __shfl_xor_sync(0xffffffffu, mB, 1));
        mB = fmaxf(mB, __shfl_xor_sync(0xffffffffu, mB, 2));
        float nmA = fmaxf(m_a, mA), nmB = fmaxf(m_b, mB);
        float corrA = ex2f(m_a - nmA), corrB = ex2f(m_b - nmB);

        float rA = 0.0f, rB = 0.0f;
#pragma unroll
        for (int tt = 0; tt < 8; tt++) {
            s[tt][0] = ex2f(s[tt][0] - nmA);
            s[tt][1] = ex2f(s[tt][1] - nmA);
            s[tt][2] = ex2f(s[tt][2] - nmB);
            s[tt][3] = ex2f(s[tt][3] - nmB);
            rA += s[tt][0] + s[tt][1];
            rB += s[tt][2] + s[tt][3];
        }
        rA += __shfl_xor_sync(0xffffffffu, rA, 1);
        rA += __shfl_xor_sync(0xffffffffu, rA, 2);
        rB += __shfl_xor_sync(0xffffffffu, rB, 1);
        rB += __shfl_xor_sync(0xffffffffu, rB, 2);
        l_a = l_a * corrA + rA;
        l_b = l_b * corrB + rB;
        m_a = nmA;
        m_b = nmB;
#pragma unroll
        for (int tt = 0; tt < 8; tt++) {
            ctx[tt][0] *= corrA;
            ctx[tt][1] *= corrA;
            ctx[tt][2] *= corrB;
            ctx[tt][3] *= corrB;
        }

        // ctx += P V  (P split in registers)
#pragma unroll
        for (int j = 0; j < 4; j++) {
            uint32_t ah[4], al[4];
            psplit(s[2 * j][0], s[2 * j][1], ah[0], al[0]);
            psplit(s[2 * j][2], s[2 * j][3], ah[1], al[1]);
            psplit(s[2 * j + 1][0], s[2 * j + 1][1], ah[2], al[2]);
            psplit(s[2 * j + 1][2], s[2 * j + 1][3], ah[3], al[3]);
#pragma unroll
            for (int hp = 0; hp < 4; hp++) {
                uint32_t vh[4], vl[4];
                uint32_t ad = ASW(j * 16 + rowV, hp * 32 + colVb);
                ldsm_x4_t(vh, VHs + ad);
                ldsm_x4_t(vl, VLs + ad);
                mma16816(ctx[2 * hp], ah, vh);
                mma16816(ctx[2 * hp], ah, vl);
                mma16816(ctx[2 * hp], al, vh);
                mma16816(ctx[2 * hp + 1], ah, vh + 2);
                mma16816(ctx[2 * hp + 1], ah, vl + 2);
                mma16816(ctx[2 * hp + 1], al, vh + 2);
            }
        }
        __syncthreads();
    }

    // epilogue
    float invA = 1.0f / l_a, invB = 1.0f / l_b;
    int qA = q0 + wid * 16 + gid;
    float* oA = out + ((size_t)b * SQ + qA) * DD + h * HDIM;
    float* oB = oA + (size_t)8 * DD;
#pragma unroll
    for (int tt = 0; tt < 8; tt++) {
        int hd = 8 * tt + 2 * tig;
        float2 a2 = make_float2(ctx[tt][0] * invA, ctx[tt][1] * invA);
        float2 b2 = make_float2(ctx[tt][2] * invB, ctx[tt][3] * invB);
        *(float2*)(oA + hd) = a2;
        *(float2*)(oB + hd) = b2;
    }
}

// ---------------------------------------------------------------------------
extern "C" void kernel_launch(void* const* d_in, const int* in_sizes, int n_in,
                              void* d_out, int out_size) {
    const float* hs = (const float*)d_in[0];
    const float* ehs = (const float*)d_in[1];
    const float* Wq = (const float*)d_in[2];
    const float* Wk = (const float*)d_in[3];
    const float* Wv = (const float*)d_in[4];
    float* out = (float*)d_out;

    bf16 *xhi, *xlo, *ehi, *elo, *wqh, *wql, *wkh, *wkl, *wvh, *wvl;
    cudaGetSymbolAddress((void**)&xhi, g_xhi);
    cudaGetSymbolAddress((void**)&xlo, g_xlo);
    cudaGetSymbolAddress((void**)&ehi, g_ehi);
    cudaGetSymbolAddress((void**)&elo, g_elo);
    cudaGetSymbolAddress((void**)&wqh, g_wqhi);
    cudaGetSymbolAddress((void**)&wql, g_wqlo);
    cudaGetSymbolAddress((void**)&wkh, g_wkhi);
    cudaGetSymbolAddress((void**)&wkl, g_wklo);
    cudaGetSymbolAddress((void**)&wvh, g_wvhi);
    cudaGetSymbolAddress((void**)&wvl, g_wvlo);

    {
        int n4 = (BB * SQ * DD) / 4;
        split_kernel<<<(n4 + 255) / 256, 256>>>(hs, xhi, xlo, n4);
        split_kernel<<<(n4 + 255) / 256, 256>>>(ehs, ehi, elo, n4);
        int w4 = (DD * DD) / 4;
        split_kernel<<<(w4 + 255) / 256, 256>>>(Wq, wqh, wql, w4);
        split_kernel<<<(w4 + 255) / 256, 256>>>(Wk, wkh, wkl, w4);
        split_kernel<<<(w4 + 255) / 256, 256>>>(Wv, wvh, wvl, w4);
    }

    {
        size_t smem = 2 * PBUF;  // 81920
        cudaFuncSetAttribute(proj_tc, cudaFuncAttributeMaxDynamicSharedMemorySize,
                             (int)smem);
        dim3 grid(DD / 128, (BB * SQ) / 128);
        proj_tc<<<grid, 256, smem>>>(xhi, xlo, wqh, wql, 0);
        proj_tc<<<grid, 256, smem>>>(ehi, elo, wkh, wkl, 1);
        proj_tc<<<grid, 256, smem>>>(ehi, elo, wvh, wvl, 2);
    }

    {
        size_t smem = 2 * QARR + 2 * KVBUF;  // 98304
        cudaFuncSetAttribute(attn_tc, cudaFuncAttributeMaxDynamicSharedMemorySize,
                             (int)smem);
        attn_tc<<<dim3(SQ / 128, HH, BB), 256, smem>>>(out);
    }
}

// round 6
// speedup vs baseline: 3.9384x; 1.1812x over previous
#include <cuda_runtime.h>
#include <cuda_bf16.h>
#include <cuda_fp16.h>
#include <cstdint>
#include <math.h>

#define BB 4
#define SQ 2048
#define SK 2048
#define DD 1024
#define HH 16
#define HDIM 64

typedef __nv_bfloat16 bf16;

// ---------------------------------------------------------------------------
// Static device scratch (no allocations anywhere)
// ---------------------------------------------------------------------------
__device__ bf16 g_xhi[(size_t)BB * SQ * DD];
__device__ bf16 g_xlo[(size_t)BB * SQ * DD];
__device__ bf16 g_ehi[(size_t)BB * SK * DD];
__device__ bf16 g_elo[(size_t)BB * SK * DD];
__device__ bf16 g_wqhi[(size_t)DD * DD];
__device__ bf16 g_wqlo[(size_t)DD * DD];
__device__ bf16 g_wkhi[(size_t)DD * DD];
__device__ bf16 g_wklo[(size_t)DD * DD];
__device__ bf16 g_wvhi[(size_t)DD * DD];
__device__ bf16 g_wvlo[(size_t)DD * DD];

// projected Q (fp16 hi/lo pair, pre-scaled by 0.125*log2e), K/V single fp16
__device__ __half g_qh[(size_t)BB * HH * SQ * HDIM];
__device__ __half g_ql[(size_t)BB * HH * SQ * HDIM];
__device__ __half g_kh[(size_t)BB * HH * SK * HDIM];
__device__ __half g_vh[(size_t)BB * HH * SK * HDIM];

// ---------------------------------------------------------------------------
// PTX helpers (baseline sm_80+ features only — harness targets plain sm_103)
// ---------------------------------------------------------------------------
__device__ __forceinline__ uint32_t smem_u32(const void* p) {
    uint32_t a;
    asm("{ .reg .u64 t; cvta.to.shared.u64 t, %1; cvt.u32.u64 %0, t; }"
        : "=r"(a) : "l"(p));
    return a;
}

__device__ __forceinline__ void cpa16(uint32_t s, const void* g) {
    asm volatile("cp.async.ca.shared.global [%0], [%1], 16;" :: "r"(s), "l"(g));
}
#define CP_COMMIT() asm volatile("cp.async.commit_group;" ::: "memory")
#define CP_WAIT(n)  asm volatile("cp.async.wait_group %0;" :: "n"(n) : "memory")

__device__ __forceinline__ void ldsm_x4(uint32_t* r, uint32_t addr) {
    asm volatile("ldmatrix.sync.aligned.m8n8.x4.shared.b16 {%0,%1,%2,%3}, [%4];"
                 : "=r"(r[0]), "=r"(r[1]), "=r"(r[2]), "=r"(r[3]) : "r"(addr));
}
__device__ __forceinline__ void ldsm_x4_t(uint32_t* r, uint32_t addr) {
    asm volatile("ldmatrix.sync.aligned.m8n8.x4.trans.shared.b16 {%0,%1,%2,%3}, [%4];"
                 : "=r"(r[0]), "=r"(r[1]), "=r"(r[2]), "=r"(r[3]) : "r"(addr));
}

// bf16 MMA (projections)
__device__ __forceinline__ void mma16816(float* c, const uint32_t* a,
                                         const uint32_t* b) {
    asm volatile(
        "mma.sync.aligned.m16n8k16.row.col.f32.bf16.bf16.f32 "
        "{%0,%1,%2,%3}, {%4,%5,%6,%7}, {%8,%9}, {%0,%1,%2,%3};"
        : "+f"(c[0]), "+f"(c[1]), "+f"(c[2]), "+f"(c[3])
        : "r"(a[0]), "r"(a[1]), "r"(a[2]), "r"(a[3]), "r"(b[0]), "r"(b[1]));
}

// fp16 MMA (attention)
__device__ __forceinline__ void mma16816h(float* c, const uint32_t* a,
                                          const uint32_t* b) {
    asm volatile(
        "mma.sync.aligned.m16n8k16.row.col.f32.f16.f16.f32 "
        "{%0,%1,%2,%3}, {%4,%5,%6,%7}, {%8,%9}, {%0,%1,%2,%3};"
        : "+f"(c[0]), "+f"(c[1]), "+f"(c[2]), "+f"(c[3])
        : "r"(a[0]), "r"(a[1]), "r"(a[2]), "r"(a[3]), "r"(b[0]), "r"(b[1]));
}

__device__ __forceinline__ float ex2f(float x) {
    float y;
    asm("ex2.approx.ftz.f32 %0, %1;" : "=f"(y) : "f"(x));
    return y;
}

// pack two fp32 into bf16x2 (lo = a, hi = b), round-to-nearest
__device__ __forceinline__ uint32_t pack_bf2(float a, float b) {
    uint32_t r;
    asm("cvt.rn.bf16x2.f32 %0, %1, %2;" : "=r"(r) : "f"(b), "f"(a));
    return r;
}

// pack two fp32 into f16x2 (lo = a, hi = b)
__device__ __forceinline__ uint32_t pack_h2(float a, float b) {
    uint32_t r;
    asm("cvt.rn.f16x2.f32 %0, %1, %2;" : "=r"(r) : "f"(b), "f"(a));
    return r;
}
__device__ __forceinline__ float h2lo(uint32_t h) {
    float f;
    asm("{ .reg .f16 l, hh; mov.b32 {l, hh}, %1; cvt.f32.f16 %0, l; }"
        : "=f"(f) : "r"(h));
    return f;
}
__device__ __forceinline__ float h2hi(uint32_t h) {
    float f;
    asm("{ .reg .f16 l, hh; mov.b32 {l, hh}, %1; cvt.f32.f16 %0, hh; }"
        : "=f"(f) : "r"(h));
    return f;
}
// split pair (s0, s1) into hi and lo f16x2 packs (s = hi + lo to ~21 bits)
__device__ __forceinline__ void psplit_h(float s0, float s1, uint32_t& h,
                                         uint32_t& l) {
    h = pack_h2(s0, s1);
    l = pack_h2(s0 - h2lo(h), s1 - h2hi(h));
}

// swizzled byte offset: 128B rows, SW128 (bits[6:4] ^= row&7)
#define ASW(row, colb) \
    ((uint32_t)(((row) << 7) + ((colb) ^ ((((uint32_t)(row)) & 7u) << 4))))

// ---------------------------------------------------------------------------
// fp32 -> (hi, lo) bf16 split of inputs
// ---------------------------------------------------------------------------
__global__ void split_kernel(const float* __restrict__ x, bf16* __restrict__ hi,
                             bf16* __restrict__ lo, int n4) {
    int i = blockIdx.x * blockDim.x + threadIdx.x;
    if (i >= n4) return;
    float4 v = ((const float4*)x)[i];
    uint32_t h0, l0, h1, l1;
    {
        uint32_t hp = pack_bf2(v.x, v.y);
        float f0 = __uint_as_float(hp << 16);
        float f1 = __uint_as_float(hp & 0xffff0000u);
        h0 = hp;
        l0 = pack_bf2(v.x - f0, v.y - f1);
    }
    {
        uint32_t hp = pack_bf2(v.z, v.w);
        float f0 = __uint_as_float(hp << 16);
        float f1 = __uint_as_float(hp & 0xffff0000u);
        h1 = hp;
        l1 = pack_bf2(v.z - f0, v.w - f1);
    }
    ((uint2*)hi)[i] = make_uint2(h0, h1);
    ((uint2*)lo)[i] = make_uint2(l0, l1);
}

// ---------------------------------------------------------------------------
// Projection GEMM (HMMA, bf16 3-term split): C[M,1024] = X @ W^T
// Block 128x128, BK=32, 256 thr (8 warps: 2m x 4n, warp tile 64x32).
// Epilogue: which==0 -> Q as fp16 hi/lo pair (pre-scaled); 1/2 -> K/V single.
// ---------------------------------------------------------------------------
#define PARR 10240u     // bytes per smem array (128 rows * 80B stride)
#define PBUF 40960u     // bytes per buffer (4 arrays)

__global__ __launch_bounds__(256) void proj_tc(
    const bf16* __restrict__ xh, const bf16* __restrict__ xl,
    const bf16* __restrict__ wh, const bf16* __restrict__ wl, int which) {
    extern __shared__ char smc[];
    const uint32_t smb = smem_u32(smc);
    const int tid = threadIdx.x;
    const int wid = tid >> 5, lane = tid & 31;
    const int gid = lane >> 2, tig = lane & 3;
    const int wm = wid & 1, wn = wid >> 1;
    const int n0 = blockIdx.x * 128;
    const int m0 = blockIdx.y * 128;

    float acc[4][4][4];
#pragma unroll
    for (int a = 0; a < 4; a++)
#pragma unroll
        for (int bq = 0; bq < 4; bq++)
#pragma unroll
            for (int c = 0; c < 4; c++) acc[a][bq][c] = 0.0f;

    auto load_tile = [&](int kc, int p) {
        const int k0 = kc * 32;
        const uint32_t base = smb + p * PBUF;
#pragma unroll
        for (int i = 0; i < 8; i++) {
            int c = tid + i * 256;
            int arr = c >> 9;
            int row = (c >> 2) & 127;
            int seg = c & 3;
            const bf16* g;
            if (arr == 0)      g = xh + (size_t)(m0 + row) * DD + k0 + seg * 8;
            else if (arr == 1) g = xl + (size_t)(m0 + row) * DD + k0 + seg * 8;
            else if (arr == 2) g = wh + (size_t)(n0 + row) * DD + k0 + seg * 8;
            else               g = wl + (size_t)(n0 + row) * DD + k0 + seg * 8;
            cpa16(base + arr * PARR + row * 80 + seg * 16, g);
        }
        CP_COMMIT();
    };

    const int rowA = lane & 15, colA = (lane >> 4) * 8;
    const int rowB = (lane & 7) + ((lane >> 4) << 3);
    const int colB = ((lane >> 3) & 1) * 8;

    load_tile(0, 0);
    for (int t = 0; t < 32; t++) {
        if (t + 1 < 32) {
            load_tile(t + 1, (t + 1) & 1);
            CP_WAIT(1);
        } else {
            CP_WAIT(0);
        }
        __syncthreads();

        const uint32_t bbase = smb + (t & 1) * PBUF;
        const uint32_t Xh_s = bbase, Xl_s = bbase + PARR;
        const uint32_t Wh_s = bbase + 2 * PARR, Wl_s = bbase + 3 * PARR;

#pragma unroll
        for (int ks = 0; ks < 2; ks++) {
            const int k0s = ks * 16;
            uint32_t bh[2][4], bl[2][4];
#pragma unroll
            for (int np = 0; np < 2; np++) {
                uint32_t ad = (wn * 32 + np * 16 + rowB) * 80 + (k0s + colB) * 2;
                ldsm_x4(bh[np], Wh_s + ad);
                ldsm_x4(bl[np], Wl_s + ad);
            }
#pragma unroll
            for (int mt = 0; mt < 4; mt++) {
                uint32_t ah[4], al[4];
                uint32_t ad = (wm * 64 + mt * 16 + rowA) * 80 + (k0s + colA) * 2;
                ldsm_x4(ah, Xh_s + ad);
                ldsm_x4(al, Xl_s + ad);
#pragma unroll
                for (int nt = 0; nt < 4; nt++) {
                    const uint32_t* bhp = &bh[nt >> 1][(nt & 1) * 2];
                    const uint32_t* blp = &bl[nt >> 1][(nt & 1) * 2];
                    mma16816(acc[mt][nt], ah, bhp);
                    mma16816(acc[mt][nt], ah, blp);
                    mma16816(acc[mt][nt], al, bhp);
                }
            }
        }
        __syncthreads();
    }

    // epilogue: fp16 write into head layout
    __half* dh = (which == 0) ? g_qh : (which == 1) ? g_kh : g_vh;
    const float qs = (which == 0) ? (0.125f * 1.4426950408889634f) : 1.0f;

#pragma unroll
    for (int mt = 0; mt < 4; mt++) {
        int m = m0 + wm * 64 + mt * 16 + gid;
        int bb = m >> 11;
        int s = m & (SQ - 1);
#pragma unroll
        for (int nt = 0; nt < 4; nt++) {
            int n = n0 + wn * 32 + nt * 8 + 2 * tig;
            int head = n >> 6;
            int hd = n & 63;
            size_t idx = (((size_t)bb * HH + head) * SQ + s) * HDIM + hd;
            if (which == 0) {
                uint32_t hp, lp;
                psplit_h(acc[mt][nt][0] * qs, acc[mt][nt][1] * qs, hp, lp);
                *(uint32_t*)(g_qh + idx) = hp;
                *(uint32_t*)(g_ql + idx) = lp;
                psplit_h(acc[mt][nt][2] * qs, acc[mt][nt][3] * qs, hp, lp);
                *(uint32_t*)(g_qh + idx + 8 * HDIM) = hp;
                *(uint32_t*)(g_ql + idx + 8 * HDIM) = lp;
            } else {
                *(uint32_t*)(dh + idx) =
                    pack_h2(acc[mt][nt][0], acc[mt][nt][1]);
                *(uint32_t*)(dh + idx + 8 * HDIM) =
                    pack_h2(acc[mt][nt][2], acc[mt][nt][3]);
            }
        }
    }
}

// ---------------------------------------------------------------------------
// Flash attention (fp16 HMMA, reduced-term split). Block = 128 q, 8 warps,
// warp = 16 q x 64 keys. Q = fp16 hi/lo (exact to 2^-21), K,V single fp16.
// QK: 2 products; PV: P split fp16 (exact), V single -> 2 products.
// smem 64KB/CTA, SW128 swizzle.
// ---------------------------------------------------------------------------
#define QARR 16384u    // 128 rows * 128B
#define KARR 8192u     // 64 rows * 128B
#define KVBUF 16384u   // 2 arrays (K, V)

__global__ __launch_bounds__(256, 2) void attn_tc(float* __restrict__ out) {
    extern __shared__ char smc[];
    const uint32_t smb = smem_u32(smc);
    const int tid = threadIdx.x;
    const int wid = tid >> 5, lane = tid & 31;
    const int gid = lane >> 2, tig = lane & 3;
    const int q0 = blockIdx.x * 128;
    const int h = blockIdx.y, b = blockIdx.z;

    const size_t bh = (size_t)b * HH + h;
    const __half* Qh_g = g_qh + (bh * SQ + q0) * HDIM;
    const __half* Ql_g = g_ql + (bh * SQ + q0) * HDIM;
    const __half* Kh_g = g_kh + bh * SK * HDIM;
    const __half* Vh_g = g_vh + bh * SK * HDIM;

    const uint32_t QH = smb, QL = smb + QARR;
    const uint32_t KV = smb + 2 * QARR;

    // Q load: 2 arrays * 128 rows * 8 segs = 2048 chunks / 256 thr = 8 each
#pragma unroll
    for (int i = 0; i < 8; i++) {
        int c = tid + i * 256;
        int arr = c >> 10;
        int row = (c >> 3) & 127;
        int seg = c & 7;
        const __half* g = (arr ? Ql_g : Qh_g) + row * HDIM + seg * 8;
        cpa16((arr ? QL : QH) + ASW(row, seg * 16), g);
    }
    CP_COMMIT();

    // KV load: 2 arrays * 64 rows * 8 segs = 1024 chunks / 256 thr = 4 each
    auto load_kv = [&](int kt, int p) {
        const uint32_t base = KV + p * KVBUF;
        const int key0 = kt * 64;
#pragma unroll
        for (int i = 0; i < 4; i++) {
            int c = tid + i * 256;
            int arr = c >> 9;
            int row = (c >> 3) & 63;
            int seg = c & 7;
            const __half* g =
                (arr ? Vh_g : Kh_g) + (size_t)(key0 + row) * HDIM + seg * 8;
            cpa16(base + arr * KARR + ASW(row, seg * 16), g);
        }
        CP_COMMIT();
    };

    load_kv(0, 0);
    CP_WAIT(1);   // Q group done; tile 0 may still be in flight
    __syncthreads();

    // preload Q fragments (hi and lo)
    const int rowA = lane & 15;
    const int colAb = (lane >> 4) * 16;
    uint32_t qh[4][4], ql[4][4];
#pragma unroll
    for (int kk = 0; kk < 4; kk++) {
        ldsm_x4(qh[kk], QH + ASW(wid * 16 + rowA, kk * 32 + colAb));
        ldsm_x4(ql[kk], QL + ASW(wid * 16 + rowA, kk * 32 + colAb));
    }

    float ctx[8][4];
#pragma unroll
    for (int t = 0; t < 8; t++)
#pragma unroll
        for (int c = 0; c < 4; c++) ctx[t][c] = 0.0f;
    float m_a = -1e30f, m_b = -1e30f, l_a = 0.0f, l_b = 0.0f;

    const int rowB = (lane & 7) + ((lane >> 4) << 3);
    const int colBb = ((lane >> 3) & 1) * 16;
    const int rowV = (lane & 7) + (((lane >> 3) & 1) << 3);
    const int colVb = (lane >> 4) * 16;

    const int NT = SK / 64;
    for (int t = 0; t < NT; t++) {
        if (t + 1 < NT) {
            load_kv(t + 1, (t + 1) & 1);
            CP_WAIT(1);
        } else {
            CP_WAIT(0);
        }
        __syncthreads();

        const uint32_t kb = KV + (t & 1) * KVBUF;
        const uint32_t KHs = kb, VHs = kb + KARR;

        // S = (Qhi + Qlo) K^T  (2 products)
        float s[8][4];
#pragma unroll
        for (int tt = 0; tt < 8; tt++)
#pragma unroll
            for (int c = 0; c < 4; c++) s[tt][c] = 0.0f;

#pragma unroll
        for (int kk = 0; kk < 4; kk++) {
#pragma unroll
            for (int nn = 0; nn < 4; nn++) {
                uint32_t kh4[4];
                ldsm_x4(kh4, KHs + ASW(nn * 16 + rowB, kk * 32 + colBb));
                mma16816h(s[2 * nn], qh[kk], kh4);
                mma16816h(s[2 * nn], ql[kk], kh4);
                mma16816h(s[2 * nn + 1], qh[kk], kh4 + 2);
                mma16816h(s[2 * nn + 1], ql[kk], kh4 + 2);
            }
        }

        // online softmax (log2 domain via pre-scaled Q)
        float mA = s[0][0], mB = s[0][2];
#pragma unroll
        for (int tt = 0; tt < 8; tt++) {
            mA = fmaxf(mA, fmaxf(s[tt][0], s[tt][1]));
            mB = fmaxf(mB, fmaxf(s[tt][2], s[tt][3]));
        }
        mA = fmaxf(mA, __shfl_xor_sync(0xffffffffu, mA, 1));
        mA = fmaxf(mA, __shfl_xor_sync(0xffffffffu, mA, 2));
        mB = fmaxf(mB, __shfl_xor_sync(0xffffffffu, mB, 1));
        mB = fmaxf(mB, __shfl_xor_sync(0xffffffffu, mB, 2));
        float nmA = fmaxf(m_a, mA), nmB = fmaxf(m_b, mB);
        float corrA = ex2f(m_a - nmA), corrB = ex2f(m_b - nmB);

        float rA = 0.0f, rB = 0.0f;
#pragma unroll
        for (int tt = 0; tt < 8; tt++) {
            s[tt][0] = ex2f(s[tt][0] - nmA);
            s[tt][1] = ex2f(s[tt][1] - nmA);
            s[tt][2] = ex2f(s[tt][2] - nmB);
            s[tt][3] = ex2f(s[tt][3] - nmB);
            rA += s[tt][0] + s[tt][1];
            rB += s[tt][2] + s[tt][3];
        }
        rA += __shfl_xor_sync(0xffffffffu, rA, 1);
        rA += __shfl_xor_sync(0xffffffffu, rA, 2);
        rB += __shfl_xor_sync(0xffffffffu, rB, 1);
        rB += __shfl_xor_sync(0xffffffffu, rB, 2);
        l_a = l_a * corrA + rA;
        l_b = l_b * corrB + rB;
        m_a = nmA;
        m_b = nmB;
#pragma unroll
        for (int tt = 0; tt < 8; tt++) {
            ctx[tt][0] *= corrA;
            ctx[tt][1] *= corrA;
            ctx[tt][2] *= corrB;
            ctx[tt][3] *= corrB;
        }

        // ctx += (Phi + Plo) V  (2 products; V single fp16)
#pragma unroll
        for (int j = 0; j < 4; j++) {
            uint32_t ah[4], al[4];
            psplit_h(s[2 * j][0], s[2 * j][1], ah[0], al[0]);
            psplit_h(s[2 * j][2], s[2 * j][3], ah[1], al[1]);
            psplit_h(s[2 * j + 1][0], s[2 * j + 1][1], ah[2], al[2]);
            psplit_h(s[2 * j + 1][2], s[2 * j + 1][3], ah[3], al[3]);
#pragma unroll
            for (int hp = 0; hp < 4; hp++) {
                uint32_t vh4[4];
                ldsm_x4_t(vh4, VHs + ASW(j * 16 + rowV, hp * 32 + colVb));
                mma16816h(ctx[2 * hp], ah, vh4);
                mma16816h(ctx[2 * hp], al, vh4);
                mma16816h(ctx[2 * hp + 1], ah, vh4 + 2);
                mma16816h(ctx[2 * hp + 1], al, vh4 + 2);
            }
        }
        __syncthreads();
    }

    // epilogue
    float invA = 1.0f / l_a, invB = 1.0f / l_b;
    int qA = q0 + wid * 16 + gid;
    float* oA = out + ((size_t)b * SQ + qA) * DD + h * HDIM;
    float* oB = oA + (size_t)8 * DD;
#pragma unroll
    for (int tt = 0; tt < 8; tt++) {
        int hd = 8 * tt + 2 * tig;
        float2 a2 = make_float2(ctx[tt][0] * invA, ctx[tt][1] * invA);
        float2 b2 = make_float2(ctx[tt][2] * invB, ctx[tt][3] * invB);
        *(float2*)(oA + hd) = a2;
        *(float2*)(oB + hd) = b2;
    }
}

// ---------------------------------------------------------------------------
extern "C" void kernel_launch(void* const* d_in, const int* in_sizes, int n_in,
                              void* d_out, int out_size) {
    const float* hs = (const float*)d_in[0];
    const float* ehs = (const float*)d_in[1];
    const float* Wq = (const float*)d_in[2];
    const float* Wk = (const float*)d_in[3];
    const float* Wv = (const float*)d_in[4];
    float* out = (float*)d_out;

    bf16 *xhi, *xlo, *ehi, *elo, *wqh, *wql, *wkh, *wkl, *wvh, *wvl;
    cudaGetSymbolAddress((void**)&xhi, g_xhi);
    cudaGetSymbolAddress((void**)&xlo, g_xlo);
    cudaGetSymbolAddress((void**)&ehi, g_ehi);
    cudaGetSymbolAddress((void**)&elo, g_elo);
    cudaGetSymbolAddress((void**)&wqh, g_wqhi);
    cudaGetSymbolAddress((void**)&wql, g_wqlo);
    cudaGetSymbolAddress((void**)&wkh, g_wkhi);
    cudaGetSymbolAddress((void**)&wkl, g_wklo);
    cudaGetSymbolAddress((void**)&wvh, g_wvhi);
    cudaGetSymbolAddress((void**)&wvl, g_wvlo);

    {
        int n4 = (BB * SQ * DD) / 4;
        split_kernel<<<(n4 + 255) / 256, 256>>>(hs, xhi, xlo, n4);
        split_kernel<<<(n4 + 255) / 256, 256>>>(ehs, ehi, elo, n4);
        int w4 = (DD * DD) / 4;
        split_kernel<<<(w4 + 255) / 256, 256>>>(Wq, wqh, wql, w4);
        split_kernel<<<(w4 + 255) / 256, 256>>>(Wk, wkh, wkl, w4);
        split_kernel<<<(w4 + 255) / 256, 256>>>(Wv, wvh, wvl, w4);
    }

    {
        size_t smem = 2 * PBUF;  // 81920
        cudaFuncSetAttribute(proj_tc, cudaFuncAttributeMaxDynamicSharedMemorySize,
                             (int)smem);
        dim3 grid(DD / 128, (BB * SQ) / 128);
        proj_tc<<<grid, 256, smem>>>(xhi, xlo, wqh, wql, 0);
        proj_tc<<<grid, 256, smem>>>(ehi, elo, wkh, wkl, 1);
        proj_tc<<<grid, 256, smem>>>(ehi, elo, wvh, wvl, 2);
    }

    {
        size_t smem = 2 * QARR + 2 * KVBUF;  // 65536
        cudaFuncSetAttribute(attn_tc, cudaFuncAttributeMaxDynamicSharedMemorySize,
                             (int)smem);
        attn_tc<<<dim3(SQ / 128, HH, BB), 256, smem>>>(out);
    }
}

// round 7
// speedup vs baseline: 5.8263x; 1.4794x over previous
#include <cuda_runtime.h>
#include <cuda_bf16.h>
#include <cuda_fp16.h>
#include <cstdint>
#include <math.h>

#define BB 4
#define SQ 2048
#define SK 2048
#define DD 1024
#define HH 16
#define HDIM 64

// ---------------------------------------------------------------------------
// Static device scratch (no allocations anywhere)
// ---------------------------------------------------------------------------
__device__ __half g_xh[(size_t)BB * SQ * DD];   // hidden_states hi
__device__ __half g_xl[(size_t)BB * SQ * DD];   // hidden_states lo
__device__ __half g_eh[(size_t)BB * SK * DD];   // encoder hi
__device__ __half g_el[(size_t)BB * SK * DD];   // encoder lo
__device__ __half g_wq[(size_t)DD * DD];        // weights single fp16
__device__ __half g_wk[(size_t)DD * DD];
__device__ __half g_wv[(size_t)DD * DD];

// projected Q/K/V in [B,H,S,HD] layout, single fp16 (Q pre-scaled 0.125*log2e)
__device__ __half g_qh[(size_t)BB * HH * SQ * HDIM];
__device__ __half g_kh[(size_t)BB * HH * SK * HDIM];
__device__ __half g_vh[(size_t)BB * HH * SK * HDIM];

// ---------------------------------------------------------------------------
// PTX helpers (baseline sm_80+ features only — harness targets plain sm_103)
// ---------------------------------------------------------------------------
__device__ __forceinline__ uint32_t smem_u32(const void* p) {
    uint32_t a;
    asm("{ .reg .u64 t; cvta.to.shared.u64 t, %1; cvt.u32.u64 %0, t; }"
        : "=r"(a) : "l"(p));
    return a;
}

__device__ __forceinline__ void cpa16(uint32_t s, const void* g) {
    asm volatile("cp.async.ca.shared.global [%0], [%1], 16;" :: "r"(s), "l"(g));
}
#define CP_COMMIT() asm volatile("cp.async.commit_group;" ::: "memory")
#define CP_WAIT(n)  asm volatile("cp.async.wait_group %0;" :: "n"(n) : "memory")

__device__ __forceinline__ void ldsm_x4(uint32_t* r, uint32_t addr) {
    asm volatile("ldmatrix.sync.aligned.m8n8.x4.shared.b16 {%0,%1,%2,%3}, [%4];"
                 : "=r"(r[0]), "=r"(r[1]), "=r"(r[2]), "=r"(r[3]) : "r"(addr));
}
__device__ __forceinline__ void ldsm_x4_t(uint32_t* r, uint32_t addr) {
    asm volatile("ldmatrix.sync.aligned.m8n8.x4.trans.shared.b16 {%0,%1,%2,%3}, [%4];"
                 : "=r"(r[0]), "=r"(r[1]), "=r"(r[2]), "=r"(r[3]) : "r"(addr));
}

// fp16 MMA
__device__ __forceinline__ void mma16816h(float* c, const uint32_t* a,
                                          const uint32_t* b) {
    asm volatile(
        "mma.sync.aligned.m16n8k16.row.col.f32.f16.f16.f32 "
        "{%0,%1,%2,%3}, {%4,%5,%6,%7}, {%8,%9}, {%0,%1,%2,%3};"
        : "+f"(c[0]), "+f"(c[1]), "+f"(c[2]), "+f"(c[3])
        : "r"(a[0]), "r"(a[1]), "r"(a[2]), "r"(a[3]), "r"(b[0]), "r"(b[1]));
}

__device__ __forceinline__ float ex2f(float x) {
    float y;
    asm("ex2.approx.ftz.f32 %0, %1;" : "=f"(y) : "f"(x));
    return y;
}

// pack two fp32 into f16x2 (lo = a, hi = b)
__device__ __forceinline__ uint32_t pack_h2(float a, float b) {
    uint32_t r;
    asm("cvt.rn.f16x2.f32 %0, %1, %2;" : "=r"(r) : "f"(b), "f"(a));
    return r;
}
__device__ __forceinline__ float h2lo(uint32_t h) {
    float f;
    asm("{ .reg .f16 l, hh; mov.b32 {l, hh}, %1; cvt.f32.f16 %0, l; }"
        : "=f"(f) : "r"(h));
    return f;
}
__device__ __forceinline__ float h2hi(uint32_t h) {
    float f;
    asm("{ .reg .f16 l, hh; mov.b32 {l, hh}, %1; cvt.f32.f16 %0, hh; }"
        : "=f"(f) : "r"(h));
    return f;
}

// swizzled byte offset: 128B rows, SW128 (bits[6:4] ^= row&7)
#define ASW(row, colb) \
    ((uint32_t)(((row) << 7) + ((colb) ^ ((((uint32_t)(row)) & 7u) << 4))))

// ---------------------------------------------------------------------------
// fp32 -> (hi, lo) fp16 split (activations: exact to ~22 bits)
// ---------------------------------------------------------------------------
__global__ void splith_kernel(const float* __restrict__ x,
                              __half* __restrict__ hi,
                              __half* __restrict__ lo, int n4) {
    int i = blockIdx.x * blockDim.x + threadIdx.x;
    if (i >= n4) return;
    float4 v = ((const float4*)x)[i];
    uint32_t h0 = pack_h2(v.x, v.y);
    uint32_t l0 = pack_h2(v.x - h2lo(h0), v.y - h2hi(h0));
    uint32_t h1 = pack_h2(v.z, v.w);
    uint32_t l1 = pack_h2(v.z - h2lo(h1), v.w - h2hi(h1));
    ((uint2*)hi)[i] = make_uint2(h0, h1);
    ((uint2*)lo)[i] = make_uint2(l0, l1);
}

// fp32 -> single fp16 (weights)
__global__ void convh_kernel(const float* __restrict__ x,
                             __half* __restrict__ y, int n4) {
    int i = blockIdx.x * blockDim.x + threadIdx.x;
    if (i >= n4) return;
    float4 v = ((const float4*)x)[i];
    ((uint2*)y)[i] = make_uint2(pack_h2(v.x, v.y), pack_h2(v.z, v.w));
}

// ---------------------------------------------------------------------------
// Projection GEMM (fp16 HMMA, 2-term: (Xhi+Xlo) @ W^T): C[M,1024]
// Block 128x128, BK=32, 256 thr (8 warps: 2m x 4n, warp tile 64x32).
// Epilogue: single fp16 into head layout (Q pre-scaled by 0.125*log2e).
// ---------------------------------------------------------------------------
#define PARR 10240u     // bytes per smem array (128 rows * 80B stride)
#define PBUF 30720u     // bytes per buffer (3 arrays: Xh, Xl, W)

__global__ __launch_bounds__(256) void proj_tc(
    const __half* __restrict__ xh, const __half* __restrict__ xl,
    const __half* __restrict__ w, int which) {
    extern __shared__ char smc[];
    const uint32_t smb = smem_u32(smc);
    const int tid = threadIdx.x;
    const int wid = tid >> 5, lane = tid & 31;
    const int gid = lane >> 2, tig = lane & 3;
    const int wm = wid & 1, wn = wid >> 1;
    const int n0 = blockIdx.x * 128;
    const int m0 = blockIdx.y * 128;

    float acc[4][4][4];
#pragma unroll
    for (int a = 0; a < 4; a++)
#pragma unroll
        for (int bq = 0; bq < 4; bq++)
#pragma unroll
            for (int c = 0; c < 4; c++) acc[a][bq][c] = 0.0f;

    // loader: 3 arrays * 128 rows * 4 segs(16B) = 1536 chunks / 256 thr = 6
    auto load_tile = [&](int kc, int p) {
        const int k0 = kc * 32;
        const uint32_t base = smb + p * PBUF;
#pragma unroll
        for (int i = 0; i < 6; i++) {
            int c = tid + i * 256;
            int arr = c >> 9;
            int row = (c >> 2) & 127;
            int seg = c & 3;
            const __half* g;
            if (arr == 0)      g = xh + (size_t)(m0 + row) * DD + k0 + seg * 8;
            else if (arr == 1) g = xl + (size_t)(m0 + row) * DD + k0 + seg * 8;
            else               g = w + (size_t)(n0 + row) * DD + k0 + seg * 8;
            cpa16(base + arr * PARR + row * 80 + seg * 16, g);
        }
        CP_COMMIT();
    };

    const int rowA = lane & 15, colA = (lane >> 4) * 8;
    const int rowB = (lane & 7) + ((lane >> 4) << 3);
    const int colB = ((lane >> 3) & 1) * 8;

    load_tile(0, 0);
    for (int t = 0; t < 32; t++) {
        if (t + 1 < 32) {
            load_tile(t + 1, (t + 1) & 1);
            CP_WAIT(1);
        } else {
            CP_WAIT(0);
        }
        __syncthreads();

        const uint32_t bbase = smb + (t & 1) * PBUF;
        const uint32_t Xh_s = bbase, Xl_s = bbase + PARR;
        const uint32_t W_s = bbase + 2 * PARR;

#pragma unroll
        for (int ks = 0; ks < 2; ks++) {
            const int k0s = ks * 16;
            uint32_t bw[2][4];
#pragma unroll
            for (int np = 0; np < 2; np++) {
                uint32_t ad = (wn * 32 + np * 16 + rowB) * 80 + (k0s + colB) * 2;
                ldsm_x4(bw[np], W_s + ad);
            }
#pragma unroll
            for (int mt = 0; mt < 4; mt++) {
                uint32_t ah[4], al[4];
                uint32_t ad = (wm * 64 + mt * 16 + rowA) * 80 + (k0s + colA) * 2;
                ldsm_x4(ah, Xh_s + ad);
                ldsm_x4(al, Xl_s + ad);
#pragma unroll
                for (int nt = 0; nt < 4; nt++) {
                    const uint32_t* bp = &bw[nt >> 1][(nt & 1) * 2];
                    mma16816h(acc[mt][nt], ah, bp);
                    mma16816h(acc[mt][nt], al, bp);
                }
            }
        }
        __syncthreads();
    }

    // epilogue: single fp16 write into head layout
    __half* dh = (which == 0) ? g_qh : (which == 1) ? g_kh : g_vh;
    const float qs = (which == 0) ? (0.125f * 1.4426950408889634f) : 1.0f;

#pragma unroll
    for (int mt = 0; mt < 4; mt++) {
        int m = m0 + wm * 64 + mt * 16 + gid;
        int bb = m >> 11;
        int s = m & (SQ - 1);
#pragma unroll
        for (int nt = 0; nt < 4; nt++) {
            int n = n0 + wn * 32 + nt * 8 + 2 * tig;
            int head = n >> 6;
            int hd = n & 63;
            size_t idx = (((size_t)bb * HH + head) * SQ + s) * HDIM + hd;
            *(uint32_t*)(dh + idx) =
                pack_h2(acc[mt][nt][0] * qs, acc[mt][nt][1] * qs);
            *(uint32_t*)(dh + idx + 8 * HDIM) =
                pack_h2(acc[mt][nt][2] * qs, acc[mt][nt][3] * qs);
        }
    }
}

// ---------------------------------------------------------------------------
// Flash attention (fp16 HMMA, single-term). Block = 128 q, 8 warps,
// warp = 16 q x 64 keys. Q, K, V, P all single fp16; fp32 accumulate.
// smem 48KB/CTA, SW128 swizzle.
// ---------------------------------------------------------------------------
#define QARR 16384u    // 128 rows * 128B
#define KARR 8192u     // 64 rows * 128B
#define KVBUF 16384u   // 2 arrays (K, V)

__global__ __launch_bounds__(256, 2) void attn_tc(float* __restrict__ out) {
    extern __shared__ char smc[];
    const uint32_t smb = smem_u32(smc);
    const int tid = threadIdx.x;
    const int wid = tid >> 5, lane = tid & 31;
    const int gid = lane >> 2, tig = lane & 3;
    const int q0 = blockIdx.x * 128;
    const int h = blockIdx.y, b = blockIdx.z;

    const size_t bh = (size_t)b * HH + h;
    const __half* Qh_g = g_qh + (bh * SQ + q0) * HDIM;
    const __half* Kh_g = g_kh + bh * SK * HDIM;
    const __half* Vh_g = g_vh + bh * SK * HDIM;

    const uint32_t QH = smb;
    const uint32_t KV = smb + QARR;

    // Q load: 128 rows * 8 segs = 1024 chunks / 256 thr = 4 each
#pragma unroll
    for (int i = 0; i < 4; i++) {
        int c = tid + i * 256;
        int row = (c >> 3) & 127;
        int seg = c & 7;
        cpa16(QH + ASW(row, seg * 16), Qh_g + row * HDIM + seg * 8);
    }
    CP_COMMIT();

    // KV load: 2 arrays * 64 rows * 8 segs = 1024 chunks / 256 thr = 4 each
    auto load_kv = [&](int kt, int p) {
        const uint32_t base = KV + p * KVBUF;
        const int key0 = kt * 64;
#pragma unroll
        for (int i = 0; i < 4; i++) {
            int c = tid + i * 256;
            int arr = c >> 9;
            int row = (c >> 3) & 63;
            int seg = c & 7;
            const __half* g =
                (arr ? Vh_g : Kh_g) + (size_t)(key0 + row) * HDIM + seg * 8;
            cpa16(base + arr * KARR + ASW(row, seg * 16), g);
        }
        CP_COMMIT();
    };

    load_kv(0, 0);
    CP_WAIT(1);   // Q group done; tile 0 may still be in flight
    __syncthreads();

    // preload Q fragments
    const int rowA = lane & 15;
    const int colAb = (lane >> 4) * 16;
    uint32_t qh[4][4];
#pragma unroll
    for (int kk = 0; kk < 4; kk++)
        ldsm_x4(qh[kk], QH + ASW(wid * 16 + rowA, kk * 32 + colAb));

    float ctx[8][4];
#pragma unroll
    for (int t = 0; t < 8; t++)
#pragma unroll
        for (int c = 0; c < 4; c++) ctx[t][c] = 0.0f;
    float m_a = -1e30f, m_b = -1e30f, l_a = 0.0f, l_b = 0.0f;

    const int rowB = (lane & 7) + ((lane >> 4) << 3);
    const int colBb = ((lane >> 3) & 1) * 16;
    const int rowV = (lane & 7) + (((lane >> 3) & 1) << 3);
    const int colVb = (lane >> 4) * 16;

    const int NT = SK / 64;
    for (int t = 0; t < NT; t++) {
        if (t + 1 < NT) {
            load_kv(t + 1, (t + 1) & 1);
            CP_WAIT(1);
        } else {
            CP_WAIT(0);
        }
        __syncthreads();

        const uint32_t kb = KV + (t & 1) * KVBUF;
        const uint32_t KHs = kb, VHs = kb + KARR;

        // S = Q K^T (single term)
        float s[8][4];
#pragma unroll
        for (int tt = 0; tt < 8; tt++)
#pragma unroll
            for (int c = 0; c < 4; c++) s[tt][c] = 0.0f;

#pragma unroll
        for (int kk = 0; kk < 4; kk++) {
#pragma unroll
            for (int nn = 0; nn < 4; nn++) {
                uint32_t kh4[4];
                ldsm_x4(kh4, KHs + ASW(nn * 16 + rowB, kk * 32 + colBb));
                mma16816h(s[2 * nn], qh[kk], kh4);
                mma16816h(s[2 * nn + 1], qh[kk], kh4 + 2);
            }
        }

        // online softmax (log2 domain via pre-scaled Q)
        float mA = s[0][0], mB = s[0][2];
#pragma unroll
        for (int tt = 0; tt < 8; tt++) {
            mA = fmaxf(mA, fmaxf(s[tt][0], s[tt][1]));
            mB = fmaxf(mB, fmaxf(s[tt][2], s[tt][3]));
        }
        mA = fmaxf(mA, __shfl_xor_sync(0xffffffffu, mA, 1));
        mA = fmaxf(mA, __shfl_xor_sync(0xffffffffu, mA, 2));
        mB = fmaxf(mB, __shfl_xor_sync(0xffffffffu, mB, 1));
        mB = fmaxf(mB, __shfl_xor_sync(0xffffffffu, mB, 2));
        float nmA = fmaxf(m_a, mA), nmB = fmaxf(m_b, mB);
        float corrA = ex2f(m_a - nmA), corrB = ex2f(m_b - nmB);

        float rA = 0.0f, rB = 0.0f;
#pragma unroll
        for (int tt = 0; tt < 8; tt++) {
            s[tt][0] = ex2f(s[tt][0] - nmA);
            s[tt][1] = ex2f(s[tt][1] - nmA);
            s[tt][2] = ex2f(s[tt][2] - nmB);
            s[tt][3] = ex2f(s[tt][3] - nmB);
            rA += s[tt][0] + s[tt][1];
            rB += s[tt][2] + s[tt][3];
        }
        rA += __shfl_xor_sync(0xffffffffu, rA, 1);
        rA += __shfl_xor_sync(0xffffffffu, rA, 2);
        rB += __shfl_xor_sync(0xffffffffu, rB, 1);
        rB += __shfl_xor_sync(0xffffffffu, rB, 2);
        l_a = l_a * corrA + rA;
        l_b = l_b * corrB + rB;
        m_a = nmA;
        m_b = nmB;
#pragma unroll
        for (int tt = 0; tt < 8; tt++) {
            ctx[tt][0] *= corrA;
            ctx[tt][1] *= corrA;
            ctx[tt][2] *= corrB;
            ctx[tt][3] *= corrB;
        }

        // ctx += P V  (single term, P single fp16)
#pragma unroll
        for (int j = 0; j < 4; j++) {
            uint32_t ah[4];
            ah[0] = pack_h2(s[2 * j][0], s[2 * j][1]);
            ah[1] = pack_h2(s[2 * j][2], s[2 * j][3]);
            ah[2] = pack_h2(s[2 * j + 1][0], s[2 * j + 1][1]);
            ah[3] = pack_h2(s[2 * j + 1][2], s[2 * j + 1][3]);
#pragma unroll
            for (int hp = 0; hp < 4; hp++) {
                uint32_t vh4[4];
                ldsm_x4_t(vh4, VHs + ASW(j * 16 + rowV, hp * 32 + colVb));
                mma16816h(ctx[2 * hp], ah, vh4);
                mma16816h(ctx[2 * hp + 1], ah, vh4 + 2);
            }
        }
        __syncthreads();
    }

    // epilogue
    float invA = 1.0f / l_a, invB = 1.0f / l_b;
    int qA = q0 + wid * 16 + gid;
    float* oA = out + ((size_t)b * SQ + qA) * DD + h * HDIM;
    float* oB = oA + (size_t)8 * DD;
#pragma unroll
    for (int tt = 0; tt < 8; tt++) {
        int hd = 8 * tt + 2 * tig;
        float2 a2 = make_float2(ctx[tt][0] * invA, ctx[tt][1] * invA);
        float2 b2 = make_float2(ctx[tt][2] * invB, ctx[tt][3] * invB);
        *(float2*)(oA + hd) = a2;
        *(float2*)(oB + hd) = b2;
    }
}

// ---------------------------------------------------------------------------
extern "C" void kernel_launch(void* const* d_in, const int* in_sizes, int n_in,
                              void* d_out, int out_size) {
    const float* hs = (const float*)d_in[0];
    const float* ehs = (const float*)d_in[1];
    const float* Wq = (const float*)d_in[2];
    const float* Wk = (const float*)d_in[3];
    const float* Wv = (const float*)d_in[4];
    float* out = (float*)d_out;

    __half *xh, *xl, *eh, *el, *wq, *wk, *wv;
    cudaGetSymbolAddress((void**)&xh, g_xh);
    cudaGetSymbolAddress((void**)&xl, g_xl);
    cudaGetSymbolAddress((void**)&eh, g_eh);
    cudaGetSymbolAddress((void**)&el, g_el);
    cudaGetSymbolAddress((void**)&wq, g_wq);
    cudaGetSymbolAddress((void**)&wk, g_wk);
    cudaGetSymbolAddress((void**)&wv, g_wv);

    {
        int n4 = (BB * SQ * DD) / 4;
        splith_kernel<<<(n4 + 255) / 256, 256>>>(hs, xh, xl, n4);
        splith_kernel<<<(n4 + 255) / 256, 256>>>(ehs, eh, el, n4);
        int w4 = (DD * DD) / 4;
        convh_kernel<<<(w4 + 255) / 256, 256>>>(Wq, wq, w4);
        convh_kernel<<<(w4 + 255) / 256, 256>>>(Wk, wk, w4);
        convh_kernel<<<(w4 + 255) / 256, 256>>>(Wv, wv, w4);
    }

    {
        size_t smem = 2 * PBUF;  // 61440
        cudaFuncSetAttribute(proj_tc, cudaFuncAttributeMaxDynamicSharedMemorySize,
                             (int)smem);
        dim3 grid(DD / 128, (BB * SQ) / 128);
        proj_tc<<<grid, 256, smem>>>(xh, xl, wq, 0);
        proj_tc<<<grid, 256, smem>>>(eh, el, wk, 1);
        proj_tc<<<grid, 256, smem>>>(eh, el, wv, 2);
    }

    {
        size_t smem = QARR + 2 * KVBUF;  // 49152
        cudaFuncSetAttribute(attn_tc, cudaFuncAttributeMaxDynamicSharedMemorySize,
                             (int)smem);
        attn_tc<<<dim3(SQ / 128, HH, BB), 256, smem>>>(out);
    }
}

// round 8
// speedup vs baseline: 7.4147x; 1.2726x over previous
#include <cuda_runtime.h>
#include <cuda_fp16.h>
#include <cstdint>
#include <math.h>

#define BB 4
#define SQ 2048
#define SK 2048
#define DD 1024
#define HH 16
#define HDIM 64

// ---------------------------------------------------------------------------
// Static device scratch (no allocations anywhere)
// ---------------------------------------------------------------------------
__device__ __half g_xh[(size_t)BB * SQ * DD];   // hidden_states fp16
__device__ __half g_eh[(size_t)BB * SK * DD];   // encoder fp16
__device__ __half g_wq[(size_t)DD * DD];        // weights fp16
__device__ __half g_wk[(size_t)DD * DD];
__device__ __half g_wv[(size_t)DD * DD];

// projected Q/K/V in [B,H,S,HD] layout, fp16 (Q pre-scaled by 0.125*log2e)
__device__ __half g_qh[(size_t)BB * HH * SQ * HDIM];
__device__ __half g_kh[(size_t)BB * HH * SK * HDIM];
__device__ __half g_vh[(size_t)BB * HH * SK * HDIM];

// ---------------------------------------------------------------------------
// PTX helpers (baseline sm_80+ features only — harness targets plain sm_103)
// ---------------------------------------------------------------------------
__device__ __forceinline__ uint32_t smem_u32(const void* p) {
    uint32_t a;
    asm("{ .reg .u64 t; cvta.to.shared.u64 t, %1; cvt.u32.u64 %0, t; }"
        : "=r"(a) : "l"(p));
    return a;
}

__device__ __forceinline__ void cpa16(uint32_t s, const void* g) {
    asm volatile("cp.async.ca.shared.global [%0], [%1], 16;" :: "r"(s), "l"(g));
}
#define CP_COMMIT() asm volatile("cp.async.commit_group;" ::: "memory")
#define CP_WAIT(n)  asm volatile("cp.async.wait_group %0;" :: "n"(n) : "memory")

__device__ __forceinline__ void ldsm_x4(uint32_t* r, uint32_t addr) {
    asm volatile("ldmatrix.sync.aligned.m8n8.x4.shared.b16 {%0,%1,%2,%3}, [%4];"
                 : "=r"(r[0]), "=r"(r[1]), "=r"(r[2]), "=r"(r[3]) : "r"(addr));
}
__device__ __forceinline__ void ldsm_x4_t(uint32_t* r, uint32_t addr) {
    asm volatile("ldmatrix.sync.aligned.m8n8.x4.trans.shared.b16 {%0,%1,%2,%3}, [%4];"
                 : "=r"(r[0]), "=r"(r[1]), "=r"(r[2]), "=r"(r[3]) : "r"(addr));
}

// fp16 MMA, fp32 accumulate
__device__ __forceinline__ void mma16816h(float* c, const uint32_t* a,
                                          const uint32_t* b) {
    asm volatile(
        "mma.sync.aligned.m16n8k16.row.col.f32.f16.f16.f32 "
        "{%0,%1,%2,%3}, {%4,%5,%6,%7}, {%8,%9}, {%0,%1,%2,%3};"
        : "+f"(c[0]), "+f"(c[1]), "+f"(c[2]), "+f"(c[3])
        : "r"(a[0]), "r"(a[1]), "r"(a[2]), "r"(a[3]), "r"(b[0]), "r"(b[1]));
}

__device__ __forceinline__ float ex2f(float x) {
    float y;
    asm("ex2.approx.ftz.f32 %0, %1;" : "=f"(y) : "f"(x));
    return y;
}

// pack two fp32 into f16x2 (lo = a, hi = b)
__device__ __forceinline__ uint32_t pack_h2(float a, float b) {
    uint32_t r;
    asm("cvt.rn.f16x2.f32 %0, %1, %2;" : "=r"(r) : "f"(b), "f"(a));
    return r;
}

// swizzled byte offset: 128B rows, SW128 (bits[6:4] ^= row&7)
#define ASW(row, colb) \
    ((uint32_t)(((row) << 7) + ((colb) ^ ((((uint32_t)(row)) & 7u) << 4))))

// ---------------------------------------------------------------------------
// fp32 -> fp16 convert
// ---------------------------------------------------------------------------
__global__ void convh_kernel(const float* __restrict__ x,
                             __half* __restrict__ y, int n4) {
    int i = blockIdx.x * blockDim.x + threadIdx.x;
    if (i >= n4) return;
    float4 v = ((const float4*)x)[i];
    ((uint2*)y)[i] = make_uint2(pack_h2(v.x, v.y), pack_h2(v.z, v.w));
}

// ---------------------------------------------------------------------------
// Projection GEMM (fp16 HMMA, single-term): C[M,1024] = X @ W^T
// Block 128x128, BK=32, 256 thr (8 warps: 2m x 4n, warp tile 64x32).
// Epilogue: fp16 into head layout (Q pre-scaled by 0.125*log2e).
// ---------------------------------------------------------------------------
#define PARR 10240u     // bytes per smem array (128 rows * 80B stride)
#define PBUF 20480u     // bytes per buffer (2 arrays: X, W)

__global__ __launch_bounds__(256) void proj_tc(
    const __half* __restrict__ x, const __half* __restrict__ w, int which) {
    extern __shared__ char smc[];
    const uint32_t smb = smem_u32(smc);
    const int tid = threadIdx.x;
    const int wid = tid >> 5, lane = tid & 31;
    const int gid = lane >> 2, tig = lane & 3;
    const int wm = wid & 1, wn = wid >> 1;
    const int n0 = blockIdx.x * 128;
    const int m0 = blockIdx.y * 128;

    float acc[4][4][4];
#pragma unroll
    for (int a = 0; a < 4; a++)
#pragma unroll
        for (int bq = 0; bq < 4; bq++)
#pragma unroll
            for (int c = 0; c < 4; c++) acc[a][bq][c] = 0.0f;

    // loader: 2 arrays * 128 rows * 4 segs(16B) = 1024 chunks / 256 thr = 4
    auto load_tile = [&](int kc, int p) {
        const int k0 = kc * 32;
        const uint32_t base = smb + p * PBUF;
#pragma unroll
        for (int i = 0; i < 4; i++) {
            int c = tid + i * 256;
            int arr = c >> 9;
            int row = (c >> 2) & 127;
            int seg = c & 3;
            const __half* g = arr ? (w + (size_t)(n0 + row) * DD + k0 + seg * 8)
                                  : (x + (size_t)(m0 + row) * DD + k0 + seg * 8);
            cpa16(base + arr * PARR + row * 80 + seg * 16, g);
        }
        CP_COMMIT();
    };

    const int rowA = lane & 15, colA = (lane >> 4) * 8;
    const int rowB = (lane & 7) + ((lane >> 4) << 3);
    const int colB = ((lane >> 3) & 1) * 8;

    load_tile(0, 0);
    for (int t = 0; t < 32; t++) {
        if (t + 1 < 32) {
            load_tile(t + 1, (t + 1) & 1);
            CP_WAIT(1);
        } else {
            CP_WAIT(0);
        }
        __syncthreads();

        const uint32_t bbase = smb + (t & 1) * PBUF;
        const uint32_t X_s = bbase;
        const uint32_t W_s = bbase + PARR;

#pragma unroll
        for (int ks = 0; ks < 2; ks++) {
            const int k0s = ks * 16;
            uint32_t bw[2][4];
#pragma unroll
            for (int np = 0; np < 2; np++) {
                uint32_t ad = (wn * 32 + np * 16 + rowB) * 80 + (k0s + colB) * 2;
                ldsm_x4(bw[np], W_s + ad);
            }
#pragma unroll
            for (int mt = 0; mt < 4; mt++) {
                uint32_t ah[4];
                uint32_t ad = (wm * 64 + mt * 16 + rowA) * 80 + (k0s + colA) * 2;
                ldsm_x4(ah, X_s + ad);
#pragma unroll
                for (int nt = 0; nt < 4; nt++) {
                    const uint32_t* bp = &bw[nt >> 1][(nt & 1) * 2];
                    mma16816h(acc[mt][nt], ah, bp);
                }
            }
        }
        __syncthreads();
    }

    // epilogue: fp16 write into head layout
    __half* dh = (which == 0) ? g_qh : (which == 1) ? g_kh : g_vh;
    const float qs = (which == 0) ? (0.125f * 1.4426950408889634f) : 1.0f;

#pragma unroll
    for (int mt = 0; mt < 4; mt++) {
        int m = m0 + wm * 64 + mt * 16 + gid;
        int bb = m >> 11;
        int s = m & (SQ - 1);
#pragma unroll
        for (int nt = 0; nt < 4; nt++) {
            int n = n0 + wn * 32 + nt * 8 + 2 * tig;
            int head = n >> 6;
            int hd = n & 63;
            size_t idx = (((size_t)bb * HH + head) * SQ + s) * HDIM + hd;
            *(uint32_t*)(dh + idx) =
                pack_h2(acc[mt][nt][0] * qs, acc[mt][nt][1] * qs);
            *(uint32_t*)(dh + idx + 8 * HDIM) =
                pack_h2(acc[mt][nt][2] * qs, acc[mt][nt][3] * qs);
        }
    }
}

// ---------------------------------------------------------------------------
// Flash attention (fp16 HMMA, single-term). Block = 128 q, 8 warps,
// warp = 16 q x 64 keys. Q, K, V, P all fp16; fp32 accumulate.
// smem 48KB/CTA, SW128 swizzle.
// ---------------------------------------------------------------------------
#define QARR 16384u    // 128 rows * 128B
#define KARR 8192u     // 64 rows * 128B
#define KVBUF 16384u   // 2 arrays (K, V)

__global__ __launch_bounds__(256, 2) void attn_tc(float* __restrict__ out) {
    extern __shared__ char smc[];
    const uint32_t smb = smem_u32(smc);
    const int tid = threadIdx.x;
    const int wid = tid >> 5, lane = tid & 31;
    const int gid = lane >> 2, tig = lane & 3;
    const int q0 = blockIdx.x * 128;
    const int h = blockIdx.y, b = blockIdx.z;

    const size_t bh = (size_t)b * HH + h;
    const __half* Qh_g = g_qh + (bh * SQ + q0) * HDIM;
    const __half* Kh_g = g_kh + bh * SK * HDIM;
    const __half* Vh_g = g_vh + bh * SK * HDIM;

    const uint32_t QH = smb;
    const uint32_t KV = smb + QARR;

    // Q load: 128 rows * 8 segs = 1024 chunks / 256 thr = 4 each
#pragma unroll
    for (int i = 0; i < 4; i++) {
        int c = tid + i * 256;
        int row = (c >> 3) & 127;
        int seg = c & 7;
        cpa16(QH + ASW(row, seg * 16), Qh_g + row * HDIM + seg * 8);
    }
    CP_COMMIT();

    // KV load: 2 arrays * 64 rows * 8 segs = 1024 chunks / 256 thr = 4 each
    auto load_kv = [&](int kt, int p) {
        const uint32_t base = KV + p * KVBUF;
        const int key0 = kt * 64;
#pragma unroll
        for (int i = 0; i < 4; i++) {
            int c = tid + i * 256;
            int arr = c >> 9;
            int row = (c >> 3) & 63;
            int seg = c & 7;
            const __half* g =
                (arr ? Vh_g : Kh_g) + (size_t)(key0 + row) * HDIM + seg * 8;
            cpa16(base + arr * KARR + ASW(row, seg * 16), g);
        }
        CP_COMMIT();
    };

    load_kv(0, 0);
    CP_WAIT(1);   // Q group done; tile 0 may still be in flight
    __syncthreads();

    // preload Q fragments
    const int rowA = lane & 15;
    const int colAb = (lane >> 4) * 16;
    uint32_t qh[4][4];
#pragma unroll
    for (int kk = 0; kk < 4; kk++)
        ldsm_x4(qh[kk], QH + ASW(wid * 16 + rowA, kk * 32 + colAb));

    float ctx[8][4];
#pragma unroll
    for (int t = 0; t < 8; t++)
#pragma unroll
        for (int c = 0; c < 4; c++) ctx[t][c] = 0.0f;
    float m_a = -1e30f, m_b = -1e30f, l_a = 0.0f, l_b = 0.0f;

    const int rowB = (lane & 7) + ((lane >> 4) << 3);
    const int colBb = ((lane >> 3) & 1) * 16;
    const int rowV = (lane & 7) + (((lane >> 3) & 1) << 3);
    const int colVb = (lane >> 4) * 16;

    const int NT = SK / 64;
    for (int t = 0; t < NT; t++) {
        if (t + 1 < NT) {
            load_kv(t + 1, (t + 1) & 1);
            CP_WAIT(1);
        } else {
            CP_WAIT(0);
        }
        __syncthreads();

        const uint32_t kb = KV + (t & 1) * KVBUF;
        const uint32_t KHs = kb, VHs = kb + KARR;

        // S = Q K^T (single term)
        float s[8][4];
#pragma unroll
        for (int tt = 0; tt < 8; tt++)
#pragma unroll
            for (int c = 0; c < 4; c++) s[tt][c] = 0.0f;

#pragma unroll
        for (int kk = 0; kk < 4; kk++) {
#pragma unroll
            for (int nn = 0; nn < 4; nn++) {
                uint32_t kh4[4];
                ldsm_x4(kh4, KHs + ASW(nn * 16 + rowB, kk * 32 + colBb));
                mma16816h(s[2 * nn], qh[kk], kh4);
                mma16816h(s[2 * nn + 1], qh[kk], kh4 + 2);
            }
        }

        // online softmax (log2 domain via pre-scaled Q)
        float mA = s[0][0], mB = s[0][2];
#pragma unroll
        for (int tt = 0; tt < 8; tt++) {
            mA = fmaxf(mA, fmaxf(s[tt][0], s[tt][1]));
            mB = fmaxf(mB, fmaxf(s[tt][2], s[tt][3]));
        }
        mA = fmaxf(mA, __shfl_xor_sync(0xffffffffu, mA, 1));
        mA = fmaxf(mA, __shfl_xor_sync(0xffffffffu, mA, 2));
        mB = fmaxf(mB, __shfl_xor_sync(0xffffffffu, mB, 1));
        mB = fmaxf(mB, __shfl_xor_sync(0xffffffffu, mB, 2));
        float nmA = fmaxf(m_a, mA), nmB = fmaxf(m_b, mB);
        float corrA = ex2f(m_a - nmA), corrB = ex2f(m_b - nmB);

        float rA = 0.0f, rB = 0.0f;
#pragma unroll
        for (int tt = 0; tt < 8; tt++) {
            s[tt][0] = ex2f(s[tt][0] - nmA);
            s[tt][1] = ex2f(s[tt][1] - nmA);
            s[tt][2] = ex2f(s[tt][2] - nmB);
            s[tt][3] = ex2f(s[tt][3] - nmB);
            rA += s[tt][0] + s[tt][1];
            rB += s[tt][2] + s[tt][3];
        }
        rA += __shfl_xor_sync(0xffffffffu, rA, 1);
        rA += __shfl_xor_sync(0xffffffffu, rA, 2);
        rB += __shfl_xor_sync(0xffffffffu, rB, 1);
        rB += __shfl_xor_sync(0xffffffffu, rB, 2);
        l_a = l_a * corrA + rA;
        l_b = l_b * corrB + rB;
        m_a = nmA;
        m_b = nmB;
#pragma unroll
        for (int tt = 0; tt < 8; tt++) {
            ctx[tt][0] *= corrA;
            ctx[tt][1] *= corrA;
            ctx[tt][2] *= corrB;
            ctx[tt][3] *= corrB;
        }

        // ctx += P V  (single term, P fp16)
#pragma unroll
        for (int j = 0; j < 4; j++) {
            uint32_t ah[4];
            ah[0] = pack_h2(s[2 * j][0], s[2 * j][1]);
            ah[1] = pack_h2(s[2 * j][2], s[2 * j][3]);
            ah[2] = pack_h2(s[2 * j + 1][0], s[2 * j + 1][1]);
            ah[3] = pack_h2(s[2 * j + 1][2], s[2 * j + 1][3]);
#pragma unroll
            for (int hp = 0; hp < 4; hp++) {
                uint32_t vh4[4];
                ldsm_x4_t(vh4, VHs + ASW(j * 16 + rowV, hp * 32 + colVb));
                mma16816h(ctx[2 * hp], ah, vh4);
                mma16816h(ctx[2 * hp + 1], ah, vh4 + 2);
            }
        }
        __syncthreads();
    }

    // epilogue
    float invA = 1.0f / l_a, invB = 1.0f / l_b;
    int qA = q0 + wid * 16 + gid;
    float* oA = out + ((size_t)b * SQ + qA) * DD + h * HDIM;
    float* oB = oA + (size_t)8 * DD;
#pragma unroll
    for (int tt = 0; tt < 8; tt++) {
        int hd = 8 * tt + 2 * tig;
        float2 a2 = make_float2(ctx[tt][0] * invA, ctx[tt][1] * invA);
        float2 b2 = make_float2(ctx[tt][2] * invB, ctx[tt][3] * invB);
        *(float2*)(oA + hd) = a2;
        *(float2*)(oB + hd) = b2;
    }
}

// ---------------------------------------------------------------------------
extern "C" void kernel_launch(void* const* d_in, const int* in_sizes, int n_in,
                              void* d_out, int out_size) {
    const float* hs = (const float*)d_in[0];
    const float* ehs = (const float*)d_in[1];
    const float* Wq = (const float*)d_in[2];
    const float* Wk = (const float*)d_in[3];
    const float* Wv = (const float*)d_in[4];
    float* out = (float*)d_out;

    __half *xh, *eh, *wq, *wk, *wv;
    cudaGetSymbolAddress((void**)&xh, g_xh);
    cudaGetSymbolAddress((void**)&eh, g_eh);
    cudaGetSymbolAddress((void**)&wq, g_wq);
    cudaGetSymbolAddress((void**)&wk, g_wk);
    cudaGetSymbolAddress((void**)&wv, g_wv);

    {
        int n4 = (BB * SQ * DD) / 4;
        convh_kernel<<<(n4 + 255) / 256, 256>>>(hs, xh, n4);
        convh_kernel<<<(n4 + 255) / 256, 256>>>(ehs, eh, n4);
        int w4 = (DD * DD) / 4;
        convh_kernel<<<(w4 + 255) / 256, 256>>>(Wq, wq, w4);
        convh_kernel<<<(w4 + 255) / 256, 256>>>(Wk, wk, w4);
        convh_kernel<<<(w4 + 255) / 256, 256>>>(Wv, wv, w4);
    }

    {
        size_t smem = 2 * PBUF;  // 40960
        cudaFuncSetAttribute(proj_tc, cudaFuncAttributeMaxDynamicSharedMemorySize,
                             (int)smem);
        dim3 grid(DD / 128, (BB * SQ) / 128);
        proj_tc<<<grid, 256, smem>>>(xh, wq, 0);
        proj_tc<<<grid, 256, smem>>>(eh, wk, 1);
        proj_tc<<<grid, 256, smem>>>(eh, wv, 2);
    }

    {
        size_t smem = QARR + 2 * KVBUF;  // 49152
        cudaFuncSetAttribute(attn_tc, cudaFuncAttributeMaxDynamicSharedMemorySize,
                             (int)smem);
        attn_tc<<<dim3(SQ / 128, HH, BB), 256, smem>>>(out);
    }
}

// round 9
// speedup vs baseline: 8.2177x; 1.1083x over previous
#include <cuda_runtime.h>
#include <cuda_fp16.h>
#include <cstdint>
#include <math.h>

#define BB 4
#define SQ 2048
#define SK 2048
#define DD 1024
#define HH 16
#define HDIM 64

// ---------------------------------------------------------------------------
// Static device scratch (no allocations anywhere)
// ---------------------------------------------------------------------------
__device__ __half g_xh[(size_t)BB * SQ * DD];   // hidden_states fp16
__device__ __half g_eh[(size_t)BB * SK * DD];   // encoder fp16
__device__ __half g_wq[(size_t)DD * DD];        // weights fp16
__device__ __half g_wk[(size_t)DD * DD];
__device__ __half g_wv[(size_t)DD * DD];

// projected Q/K/V in [B,H,S,HD] layout, fp16 (Q pre-scaled by 0.125*log2e)
__device__ __half g_qh[(size_t)BB * HH * SQ * HDIM];
__device__ __half g_kh[(size_t)BB * HH * SK * HDIM];
__device__ __half g_vh[(size_t)BB * HH * SK * HDIM];

// ---------------------------------------------------------------------------
// PTX helpers (baseline sm_80+ features only — harness targets plain sm_103)
// ---------------------------------------------------------------------------
__device__ __forceinline__ uint32_t smem_u32(const void* p) {
    uint32_t a;
    asm("{ .reg .u64 t; cvta.to.shared.u64 t, %1; cvt.u32.u64 %0, t; }"
        : "=r"(a) : "l"(p));
    return a;
}

__device__ __forceinline__ void cpa16(uint32_t s, const void* g) {
    asm volatile("cp.async.ca.shared.global [%0], [%1], 16;" :: "r"(s), "l"(g));
}
#define CP_COMMIT() asm volatile("cp.async.commit_group;" ::: "memory")
#define CP_WAIT(n)  asm volatile("cp.async.wait_group %0;" :: "n"(n) : "memory")

__device__ __forceinline__ void ldsm_x4(uint32_t* r, uint32_t addr) {
    asm volatile("ldmatrix.sync.aligned.m8n8.x4.shared.b16 {%0,%1,%2,%3}, [%4];"
                 : "=r"(r[0]), "=r"(r[1]), "=r"(r[2]), "=r"(r[3]) : "r"(addr));
}
__device__ __forceinline__ void ldsm_x4_t(uint32_t* r, uint32_t addr) {
    asm volatile("ldmatrix.sync.aligned.m8n8.x4.trans.shared.b16 {%0,%1,%2,%3}, [%4];"
                 : "=r"(r[0]), "=r"(r[1]), "=r"(r[2]), "=r"(r[3]) : "r"(addr));
}

// fp16 MMA, fp32 accumulate
__device__ __forceinline__ void mma16816h(float* c, const uint32_t* a,
                                          const uint32_t* b) {
    asm volatile(
        "mma.sync.aligned.m16n8k16.row.col.f32.f16.f16.f32 "
        "{%0,%1,%2,%3}, {%4,%5,%6,%7}, {%8,%9}, {%0,%1,%2,%3};"
        : "+f"(c[0]), "+f"(c[1]), "+f"(c[2]), "+f"(c[3])
        : "r"(a[0]), "r"(a[1]), "r"(a[2]), "r"(a[3]), "r"(b[0]), "r"(b[1]));
}

__device__ __forceinline__ float ex2f(float x) {
    float y;
    asm("ex2.approx.ftz.f32 %0, %1;" : "=f"(y) : "f"(x));
    return y;
}

// pack two fp32 into f16x2 (lo = a, hi = b)
__device__ __forceinline__ uint32_t pack_h2(float a, float b) {
    uint32_t r;
    asm("cvt.rn.f16x2.f32 %0, %1, %2;" : "=r"(r) : "f"(b), "f"(a));
    return r;
}

// swizzled byte offset: 128B rows, SW128 (bits[6:4] ^= row&7)
#define ASW(row, colb) \
    ((uint32_t)(((row) << 7) + ((colb) ^ ((((uint32_t)(row)) & 7u) << 4))))

// ---------------------------------------------------------------------------
// Fused fp32 -> fp16 convert of all five inputs (one launch)
// ---------------------------------------------------------------------------
#define NA4 ((BB * SQ * DD) / 4)   // 2097152
#define NW4 ((DD * DD) / 4)        // 262144
#define NCONV (2 * NA4 + 3 * NW4)  // 4980736

__global__ void convall_kernel(const float* __restrict__ hs,
                               const float* __restrict__ ehs,
                               const float* __restrict__ Wq,
                               const float* __restrict__ Wk,
                               const float* __restrict__ Wv) {
    int i = blockIdx.x * blockDim.x + threadIdx.x;
    if (i >= NCONV) return;
    const float* src;
    __half* dst;
    int j = i;
    if (j < NA4) {
        src = hs;  dst = g_xh;
    } else if ((j -= NA4) < NA4) {
        src = ehs; dst = g_eh;
    } else if ((j -= NA4) < NW4) {
        src = Wq;  dst = g_wq;
    } else if ((j -= NW4) < NW4) {
        src = Wk;  dst = g_wk;
    } else {
        j -= NW4;
        src = Wv;  dst = g_wv;
    }
    float4 v = ((const float4*)src)[j];
    ((uint2*)dst)[j] = make_uint2(pack_h2(v.x, v.y), pack_h2(v.z, v.w));
}

// ---------------------------------------------------------------------------
// Fused projection GEMM (fp16 HMMA): blockIdx.z = 0/1/2 -> Q/K/V.
// Block 128x128, BK=32, 256 thr (8 warps: 2m x 4n, warp tile 64x32).
// 3-stage smem ring, prefetch distance 2, one __syncthreads per k-tile.
// ---------------------------------------------------------------------------
#define PARR 10240u     // bytes per smem array (128 rows * 80B stride)
#define PBUF 20480u     // bytes per buffer (2 arrays: X, W)

__global__ __launch_bounds__(256, 2) void proj_tc() {
    extern __shared__ char smc[];
    const uint32_t smb = smem_u32(smc);
    const int tid = threadIdx.x;
    const int wid = tid >> 5, lane = tid & 31;
    const int gid = lane >> 2, tig = lane & 3;
    const int wm = wid & 1, wn = wid >> 1;
    const int n0 = blockIdx.x * 128;
    const int m0 = blockIdx.y * 128;
    const int which = blockIdx.z;

    const __half* x = (which == 0) ? g_xh : g_eh;
    const __half* w = (which == 0) ? g_wq : (which == 1) ? g_wk : g_wv;

    float acc[4][4][4];
#pragma unroll
    for (int a = 0; a < 4; a++)
#pragma unroll
        for (int bq = 0; bq < 4; bq++)
#pragma unroll
            for (int c = 0; c < 4; c++) acc[a][bq][c] = 0.0f;

    // loader: 2 arrays * 128 rows * 4 segs(16B) = 1024 chunks / 256 thr = 4
    auto load_tile = [&](int kc, int p) {
        const int k0 = kc * 32;
        const uint32_t base = smb + (uint32_t)p * PBUF;
#pragma unroll
        for (int i = 0; i < 4; i++) {
            int c = tid + i * 256;
            int arr = c >> 9;
            int row = (c >> 2) & 127;
            int seg = c & 3;
            const __half* g = arr ? (w + (size_t)(n0 + row) * DD + k0 + seg * 8)
                                  : (x + (size_t)(m0 + row) * DD + k0 + seg * 8);
            cpa16(base + arr * PARR + row * 80 + seg * 16, g);
        }
        CP_COMMIT();
    };

    const int rowA = lane & 15, colA = (lane >> 4) * 8;
    const int rowB = (lane & 7) + ((lane >> 4) << 3);
    const int colB = ((lane >> 3) & 1) * 8;

    load_tile(0, 0);
    load_tile(1, 1);
    for (int t = 0; t < 32; t++) {
        if (t + 1 < 32) {
            CP_WAIT(1);   // tile t landed; t+1 may be in flight
        } else {
            CP_WAIT(0);
        }
        __syncthreads();
        if (t + 2 < 32) load_tile(t + 2, (t + 2) % 3);

        const uint32_t bbase = smb + (uint32_t)(t % 3) * PBUF;
        const uint32_t X_s = bbase;
        const uint32_t W_s = bbase + PARR;

#pragma unroll
        for (int ks = 0; ks < 2; ks++) {
            const int k0s = ks * 16;
            uint32_t bw[2][4];
#pragma unroll
            for (int np = 0; np < 2; np++) {
                uint32_t ad = (wn * 32 + np * 16 + rowB) * 80 + (k0s + colB) * 2;
                ldsm_x4(bw[np], W_s + ad);
            }
#pragma unroll
            for (int mt = 0; mt < 4; mt++) {
                uint32_t ah[4];
                uint32_t ad = (wm * 64 + mt * 16 + rowA) * 80 + (k0s + colA) * 2;
                ldsm_x4(ah, X_s + ad);
#pragma unroll
                for (int nt = 0; nt < 4; nt++) {
                    const uint32_t* bp = &bw[nt >> 1][(nt & 1) * 2];
                    mma16816h(acc[mt][nt], ah, bp);
                }
            }
        }
    }

    // epilogue: fp16 write into head layout
    __half* dh = (which == 0) ? g_qh : (which == 1) ? g_kh : g_vh;
    const float qs = (which == 0) ? (0.125f * 1.4426950408889634f) : 1.0f;

#pragma unroll
    for (int mt = 0; mt < 4; mt++) {
        int m = m0 + wm * 64 + mt * 16 + gid;
        int bb = m >> 11;
        int s = m & (SQ - 1);
#pragma unroll
        for (int nt = 0; nt < 4; nt++) {
            int n = n0 + wn * 32 + nt * 8 + 2 * tig;
            int head = n >> 6;
            int hd = n & 63;
            size_t idx = (((size_t)bb * HH + head) * SQ + s) * HDIM + hd;
            *(uint32_t*)(dh + idx) =
                pack_h2(acc[mt][nt][0] * qs, acc[mt][nt][1] * qs);
            *(uint32_t*)(dh + idx + 8 * HDIM) =
                pack_h2(acc[mt][nt][2] * qs, acc[mt][nt][3] * qs);
        }
    }
}

// ---------------------------------------------------------------------------
// Flash attention (fp16 HMMA). Block = 128 q, 8 warps, warp = 16 q x 64 keys.
// 3-stage KV ring, prefetch distance 2, one __syncthreads per tile.
// smem 64KB/CTA, SW128 swizzle, 2 CTAs/SM.
// ---------------------------------------------------------------------------
#define QARR 16384u    // 128 rows * 128B
#define KARR 8192u     // 64 rows * 128B
#define KVBUF 16384u   // 2 arrays (K, V)

__global__ __launch_bounds__(256, 2) void attn_tc(float* __restrict__ out) {
    extern __shared__ char smc[];
    const uint32_t smb = smem_u32(smc);
    const int tid = threadIdx.x;
    const int wid = tid >> 5, lane = tid & 31;
    const int gid = lane >> 2, tig = lane & 3;
    const int q0 = blockIdx.x * 128;
    const int h = blockIdx.y, b = blockIdx.z;

    const size_t bh = (size_t)b * HH + h;
    const __half* Qh_g = g_qh + (bh * SQ + q0) * HDIM;
    const __half* Kh_g = g_kh + bh * SK * HDIM;
    const __half* Vh_g = g_vh + bh * SK * HDIM;

    const uint32_t QH = smb;
    const uint32_t KV = smb + QARR;

    // Q load: 128 rows * 8 segs = 1024 chunks / 256 thr = 4 each
#pragma unroll
    for (int i = 0; i < 4; i++) {
        int c = tid + i * 256;
        int row = (c >> 3) & 127;
        int seg = c & 7;
        cpa16(QH + ASW(row, seg * 16), Qh_g + row * HDIM + seg * 8);
    }
    CP_COMMIT();

    // KV load: 2 arrays * 64 rows * 8 segs = 1024 chunks / 256 thr = 4 each
    auto load_kv = [&](int kt, int p) {
        const uint32_t base = KV + (uint32_t)p * KVBUF;
        const int key0 = kt * 64;
#pragma unroll
        for (int i = 0; i < 4; i++) {
            int c = tid + i * 256;
            int arr = c >> 9;
            int row = (c >> 3) & 63;
            int seg = c & 7;
            const __half* g =
                (arr ? Vh_g : Kh_g) + (size_t)(key0 + row) * HDIM + seg * 8;
            cpa16(base + arr * KARR + ASW(row, seg * 16), g);
        }
        CP_COMMIT();
    };

    load_kv(0, 0);
    load_kv(1, 1);
    CP_WAIT(2);   // Q group complete; kv0/kv1 may be in flight
    __syncthreads();

    // preload Q fragments
    const int rowA = lane & 15;
    const int colAb = (lane >> 4) * 16;
    uint32_t qh[4][4];
#pragma unroll
    for (int kk = 0; kk < 4; kk++)
        ldsm_x4(qh[kk], QH + ASW(wid * 16 + rowA, kk * 32 + colAb));

    float ctx[8][4];
#pragma unroll
    for (int t = 0; t < 8; t++)
#pragma unroll
        for (int c = 0; c < 4; c++) ctx[t][c] = 0.0f;
    float m_a = -1e30f, m_b = -1e30f, l_a = 0.0f, l_b = 0.0f;

    const int rowB = (lane & 7) + ((lane >> 4) << 3);
    const int colBb = ((lane >> 3) & 1) * 16;
    const int rowV = (lane & 7) + (((lane >> 3) & 1) << 3);
    const int colVb = (lane >> 4) * 16;

    const int NT = SK / 64;
    for (int t = 0; t < NT; t++) {
        if (t + 1 < NT) {
            CP_WAIT(1);   // tile t landed; t+1 in flight
        } else {
            CP_WAIT(0);
        }
        __syncthreads();
        if (t + 2 < NT) load_kv(t + 2, (t + 2) % 3);

        const uint32_t kb = KV + (uint32_t)(t % 3) * KVBUF;
        const uint32_t KHs = kb, VHs = kb + KARR;

        // S = Q K^T (single term)
        float s[8][4];
#pragma unroll
        for (int tt = 0; tt < 8; tt++)
#pragma unroll
            for (int c = 0; c < 4; c++) s[tt][c] = 0.0f;

#pragma unroll
        for (int kk = 0; kk < 4; kk++) {
#pragma unroll
            for (int nn = 0; nn < 4; nn++) {
                uint32_t kh4[4];
                ldsm_x4(kh4, KHs + ASW(nn * 16 + rowB, kk * 32 + colBb));
                mma16816h(s[2 * nn], qh[kk], kh4);
                mma16816h(s[2 * nn + 1], qh[kk], kh4 + 2);
            }
        }

        // online softmax (log2 domain via pre-scaled Q)
        float mA = s[0][0], mB = s[0][2];
#pragma unroll
        for (int tt = 0; tt < 8; tt++) {
            mA = fmaxf(mA, fmaxf(s[tt][0], s[tt][1]));
            mB = fmaxf(mB, fmaxf(s[tt][2], s[tt][3]));
        }
        mA = fmaxf(mA, __shfl_xor_sync(0xffffffffu, mA, 1));
        mA = fmaxf(mA, __shfl_xor_sync(0xffffffffu, mA, 2));
        mB = fmaxf(mB, __shfl_xor_sync(0xffffffffu, mB, 1));
        mB = fmaxf(mB, __shfl_xor_sync(0xffffffffu, mB, 2));
        float nmA = fmaxf(m_a, mA), nmB = fmaxf(m_b, mB);
        float corrA = ex2f(m_a - nmA), corrB = ex2f(m_b - nmB);

        float rA = 0.0f, rB = 0.0f;
#pragma unroll
        for (int tt = 0; tt < 8; tt++) {
            s[tt][0] = ex2f(s[tt][0] - nmA);
            s[tt][1] = ex2f(s[tt][1] - nmA);
            s[tt][2] = ex2f(s[tt][2] - nmB);
            s[tt][3] = ex2f(s[tt][3] - nmB);
            rA += s[tt][0] + s[tt][1];
            rB += s[tt][2] + s[tt][3];
        }
        rA += __shfl_xor_sync(0xffffffffu, rA, 1);
        rA += __shfl_xor_sync(0xffffffffu, rA, 2);
        rB += __shfl_xor_sync(0xffffffffu, rB, 1);
        rB += __shfl_xor_sync(0xffffffffu, rB, 2);
        l_a = l_a * corrA + rA;
        l_b = l_b * corrB + rB;
        m_a = nmA;
        m_b = nmB;
#pragma unroll
        for (int tt = 0; tt < 8; tt++) {
            ctx[tt][0] *= corrA;
            ctx[tt][1] *= corrA;
            ctx[tt][2] *= corrB;
            ctx[tt][3] *= corrB;
        }

        // ctx += P V  (P fp16)
#pragma unroll
        for (int j = 0; j < 4; j++) {
            uint32_t ah[4];
            ah[0] = pack_h2(s[2 * j][0], s[2 * j][1]);
            ah[1] = pack_h2(s[2 * j][2], s[2 * j][3]);
            ah[2] = pack_h2(s[2 * j + 1][0], s[2 * j + 1][1]);
            ah[3] = pack_h2(s[2 * j + 1][2], s[2 * j + 1][3]);
#pragma unroll
            for (int hp = 0; hp < 4; hp++) {
                uint32_t vh4[4];
                ldsm_x4_t(vh4, VHs + ASW(j * 16 + rowV, hp * 32 + colVb));
                mma16816h(ctx[2 * hp], ah, vh4);
                mma16816h(ctx[2 * hp + 1], ah, vh4 + 2);
            }
        }
    }

    // epilogue
    float invA = 1.0f / l_a, invB = 1.0f / l_b;
    int qA = q0 + wid * 16 + gid;
    float* oA = out + ((size_t)b * SQ + qA) * DD + h * HDIM;
    float* oB = oA + (size_t)8 * DD;
#pragma unroll
    for (int tt = 0; tt < 8; tt++) {
        int hd = 8 * tt + 2 * tig;
        float2 a2 = make_float2(ctx[tt][0] * invA, ctx[tt][1] * invA);
        float2 b2 = make_float2(ctx[tt][2] * invB, ctx[tt][3] * invB);
        *(float2*)(oA + hd) = a2;
        *(float2*)(oB + hd) = b2;
    }
}

// ---------------------------------------------------------------------------
extern "C" void kernel_launch(void* const* d_in, const int* in_sizes, int n_in,
                              void* d_out, int out_size) {
    const float* hs = (const float*)d_in[0];
    const float* ehs = (const float*)d_in[1];
    const float* Wq = (const float*)d_in[2];
    const float* Wk = (const float*)d_in[3];
    const float* Wv = (const float*)d_in[4];
    float* out = (float*)d_out;

    // single fused convert launch
    convall_kernel<<<(NCONV + 255) / 256, 256>>>(hs, ehs, Wq, Wk, Wv);

    // single fused projection launch (Q, K, V via blockIdx.z)
    {
        size_t smem = 3 * PBUF;  // 61440
        cudaFuncSetAttribute(proj_tc, cudaFuncAttributeMaxDynamicSharedMemorySize,
                             (int)smem);
        dim3 grid(DD / 128, (BB * SQ) / 128, 3);
        proj_tc<<<grid, 256, smem>>>();
    }

    // attention
    {
        size_t smem = QARR + 3 * KVBUF;  // 65536
        cudaFuncSetAttribute(attn_tc, cudaFuncAttributeMaxDynamicSharedMemorySize,
                             (int)smem);
        attn_tc<<<dim3(SQ / 128, HH, BB), 256, smem>>>(out);
    }
}